// round 2
// baseline (speedup 1.0000x reference)
#include <cuda_runtime.h>
#include <math.h>

#define SEQ   2048
#define NXC   768
#define NH    12
#define HD    64
#define BSZ   2
#define MROWS (BSZ*SEQ)      // 4096
#define QKVN  (3*NXC)        // 2304

// Scratch (static __device__ — no allocations allowed)
__device__ float g_qkv[3ull * MROWS * NXC];   // [3][MROWS][NXC]: Q,K,V contiguous per part
__device__ float g_att[(size_t)MROWS * NXC];  // attention output [b*seq][h*64+d]

// ---------------------------------------------------------------------------
// GEMM: C[M,N] = A[M,K] @ B[K,N] + bias.  Tile 64x64, BK=16, 256 thr, 4x4/thr.
// SPLITOUT=1: scatter output columns into g_qkv (Q/K/V split).
// ATT_IN=1:   read A from g_att instead of the A argument.
// ---------------------------------------------------------------------------
template<int SPLITOUT, int ATT_IN>
__global__ void gemm_kernel(const float* __restrict__ A, const float* __restrict__ B,
                            const float* __restrict__ bias, float* __restrict__ C,
                            int M, int N, int K)
{
    __shared__ float As[16][64];   // [k][row]
    __shared__ float Bs[16][64];   // [k][col]

    const float* Ap = (ATT_IN == 1) ? g_att : A;

    int tid = threadIdx.x;
    int tx = tid & 15, ty = tid >> 4;
    int brow = blockIdx.y * 64;
    int bcol = blockIdx.x * 64;

    float acc[4][4] = {};

    int arow = tid >> 2;          // 0..63
    int akq  = (tid & 3) * 4;     // 0,4,8,12
    int bk   = tid >> 4;          // 0..15
    int bn   = (tid & 15) * 4;    // 0..60

    const float* Aptr = Ap + (size_t)(brow + arow) * K + akq;
    const float* Bptr = B  + (size_t)bk * N + bcol + bn;

    for (int k0 = 0; k0 < K; k0 += 16) {
        float4 av = *(const float4*)(Aptr + k0);
        As[akq + 0][arow] = av.x;
        As[akq + 1][arow] = av.y;
        As[akq + 2][arow] = av.z;
        As[akq + 3][arow] = av.w;
        *(float4*)&Bs[bk][bn] = *(const float4*)(Bptr + (size_t)k0 * N);
        __syncthreads();
        #pragma unroll
        for (int kk = 0; kk < 16; kk++) {
            float4 a4 = *(const float4*)&As[kk][ty * 4];
            float4 b4 = *(const float4*)&Bs[kk][tx * 4];
            float aa[4] = {a4.x, a4.y, a4.z, a4.w};
            float bb[4] = {b4.x, b4.y, b4.z, b4.w};
            #pragma unroll
            for (int i = 0; i < 4; i++)
                #pragma unroll
                for (int j = 0; j < 4; j++)
                    acc[i][j] += aa[i] * bb[j];
        }
        __syncthreads();
    }

    #pragma unroll
    for (int i = 0; i < 4; i++) {
        int row = brow + ty * 4 + i;
        #pragma unroll
        for (int j = 0; j < 4; j++) {
            int col = bcol + tx * 4 + j;
            float v = acc[i][j] + bias[col];
            if (SPLITOUT == 0) {
                C[(size_t)row * N + col] = v;
            } else {
                int part = col / NXC;                 // 0=Q,1=K,2=V
                int c = col - part * NXC;
                g_qkv[(size_t)part * MROWS * NXC + (size_t)row * NXC + c] = v;
            }
        }
    }
}

// ---------------------------------------------------------------------------
// Flash attention: one block per (qb, head, batch). 64 q-rows x 64 k-cols.
// 256 threads (16x16), 4x4 register tiles. Online softmax; masked logits
// (-10000) underflow to exact 0 => skip kb>qb tiles (bit-identical softmax).
// Dynamic smem: Qs,Ks (transposed [d][r]) + Vs [j][d] + Ps [r][j] = 64 KB.
// ---------------------------------------------------------------------------
__global__ void attn_kernel(const float* __restrict__ amask)
{
    extern __shared__ float sm[];
    float* Qs = sm;             // [64][64] as [d][r]
    float* Ks = sm + 4096;      // [64][64] as [d][c]
    float* Vs = sm + 8192;      // [64][64] as [j][d]
    float* Ps = sm + 12288;     // [64][64] as [r][j]

    int b  = blockIdx.z;
    int h  = blockIdx.y;
    int qb = gridDim.x - 1 - blockIdx.x;   // heavy (high-qb) blocks launch first
    int tid = threadIdx.x;
    int tx = tid & 15, ty = tid >> 4;

    const size_t bh = (size_t)b * SEQ * NXC + (size_t)h * SEQ * HD;
    const float* Qg = g_qkv + bh;
    const float* Kg = g_qkv + (size_t)MROWS * NXC + bh;
    const float* Vg = g_qkv + 2ull * MROWS * NXC + bh;
    const float* am = amask + (size_t)b * SEQ;

    // Load Q tile transposed
    #pragma unroll
    for (int it = 0; it < 4; it++) {
        int idx = tid + it * 256;           // 0..1023
        int r  = idx >> 4;                  // 0..63
        int dq = (idx & 15) * 4;
        float4 v = *(const float4*)(Qg + (size_t)(qb * 64 + r) * HD + dq);
        Qs[(dq + 0) * 64 + r] = v.x;
        Qs[(dq + 1) * 64 + r] = v.y;
        Qs[(dq + 2) * 64 + r] = v.z;
        Qs[(dq + 3) * 64 + r] = v.w;
    }

    float m_i[4], l_i[4], acc[4][4];
    #pragma unroll
    for (int i = 0; i < 4; i++) {
        m_i[i] = -INFINITY; l_i[i] = 0.f;
        #pragma unroll
        for (int j = 0; j < 4; j++) acc[i][j] = 0.f;
    }

    for (int kb = 0; kb <= qb; kb++) {
        __syncthreads();   // prior-iter Vs/Ps reads done before overwrite
        #pragma unroll
        for (int it = 0; it < 4; it++) {
            int idx = tid + it * 256;
            int r  = idx >> 4;
            int dq = (idx & 15) * 4;
            float4 kv = *(const float4*)(Kg + (size_t)(kb * 64 + r) * HD + dq);
            Ks[(dq + 0) * 64 + r] = kv.x;
            Ks[(dq + 1) * 64 + r] = kv.y;
            Ks[(dq + 2) * 64 + r] = kv.z;
            Ks[(dq + 3) * 64 + r] = kv.w;
            float4 vv = *(const float4*)(Vg + (size_t)(kb * 64 + r) * HD + dq);
            *(float4*)&Vs[r * 64 + dq] = vv;
        }
        __syncthreads();

        // S = Q @ K^T
        float s[4][4] = {};
        #pragma unroll 4
        for (int kk = 0; kk < 64; kk++) {
            float4 a4 = *(const float4*)&Qs[kk * 64 + ty * 4];
            float4 b4 = *(const float4*)&Ks[kk * 64 + tx * 4];
            float aa[4] = {a4.x, a4.y, a4.z, a4.w};
            float bb[4] = {b4.x, b4.y, b4.z, b4.w};
            #pragma unroll
            for (int i = 0; i < 4; i++)
                #pragma unroll
                for (int j = 0; j < 4; j++)
                    s[i][j] += aa[i] * bb[j];
        }

        // scale + causal mask (-10000) + attention_mask
        float amv[4];
        #pragma unroll
        for (int j = 0; j < 4; j++) amv[j] = am[kb * 64 + tx * 4 + j];
        #pragma unroll
        for (int i = 0; i < 4; i++) {
            int gi = qb * 64 + ty * 4 + i;
            #pragma unroll
            for (int j = 0; j < 4; j++) {
                int gj = kb * 64 + tx * 4 + j;
                float v = s[i][j] * 0.125f;
                if (gj > gi) v = -10000.0f;
                s[i][j] = v + amv[j];
            }
        }

        // Online softmax (row stats across the 16 tx lanes of each ty group)
        #pragma unroll
        for (int i = 0; i < 4; i++) {
            float rm = fmaxf(fmaxf(s[i][0], s[i][1]), fmaxf(s[i][2], s[i][3]));
            #pragma unroll
            for (int off = 8; off; off >>= 1)
                rm = fmaxf(rm, __shfl_xor_sync(0xffffffffu, rm, off));
            float mnew  = fmaxf(m_i[i], rm);
            float alpha = __expf(m_i[i] - mnew);
            float rs = 0.f;
            #pragma unroll
            for (int j = 0; j < 4; j++) {
                s[i][j] = __expf(s[i][j] - mnew);
                rs += s[i][j];
            }
            #pragma unroll
            for (int off = 8; off; off >>= 1)
                rs += __shfl_xor_sync(0xffffffffu, rs, off);
            l_i[i] = l_i[i] * alpha + rs;
            m_i[i] = mnew;
            #pragma unroll
            for (int j = 0; j < 4; j++) acc[i][j] *= alpha;
            *(float4*)&Ps[(ty * 4 + i) * 64 + tx * 4] =
                make_float4(s[i][0], s[i][1], s[i][2], s[i][3]);
        }
        __syncthreads();

        // O += P @ V
        #pragma unroll 4
        for (int jj = 0; jj < 64; jj++) {
            float4 b4 = *(const float4*)&Vs[jj * 64 + tx * 4];
            float bb[4] = {b4.x, b4.y, b4.z, b4.w};
            #pragma unroll
            for (int i = 0; i < 4; i++) {
                float p = Ps[(ty * 4 + i) * 64 + jj];
                #pragma unroll
                for (int j = 0; j < 4; j++) acc[i][j] += p * bb[j];
            }
        }
    }

    // Write O / l  ->  g_att[b*SEQ+i][h*64+d]   (merged-head layout for proj)
    #pragma unroll
    for (int i = 0; i < 4; i++) {
        int gi = qb * 64 + ty * 4 + i;
        float inv = 1.0f / l_i[i];
        float4 o = make_float4(acc[i][0] * inv, acc[i][1] * inv,
                               acc[i][2] * inv, acc[i][3] * inv);
        *(float4*)&g_att[((size_t)b * SEQ + gi) * NXC + h * HD + tx * 4] = o;
    }
}

extern "C" void kernel_launch(void* const* d_in, const int* in_sizes, int n_in,
                              void* d_out, int out_size)
{
    const float* x      = (const float*)d_in[0];  // [2,2048,768]
    const float* amask  = (const float*)d_in[1];  // [2,1,1,2048]
    const float* w_attn = (const float*)d_in[2];  // [768,2304]
    const float* b_attn = (const float*)d_in[3];  // [2304]
    const float* w_proj = (const float*)d_in[4];  // [768,768]
    const float* b_proj = (const float*)d_in[5];  // [768]
    float* out = (float*)d_out;                   // [2,2048,768]

    // 1) QKV projection, scattered into g_qkv Q/K/V parts
    gemm_kernel<1, 0><<<dim3(QKVN / 64, MROWS / 64), 256>>>(
        x, w_attn, b_attn, nullptr, MROWS, QKVN, NXC);

    // 2) Flash attention (64 KB dynamic smem)
    cudaFuncSetAttribute(attn_kernel,
                         cudaFuncAttributeMaxDynamicSharedMemorySize, 65536);
    attn_kernel<<<dim3(SEQ / 64, NH, BSZ), 256, 65536>>>(amask);

    // 3) Output projection -> d_out
    gemm_kernel<0, 1><<<dim3(NXC / 64, MROWS / 64), 256>>>(
        nullptr, w_proj, b_proj, out, MROWS, NXC, NXC);
}

// round 3
// speedup vs baseline: 2.2665x; 2.2665x over previous
#include <cuda_runtime.h>
#include <math.h>

#define SEQ   2048
#define NXC   768
#define NH    12
#define HD    64
#define BSZ   2
#define MROWS (BSZ*SEQ)      // 4096
#define QKVN  (3*NXC)        // 2304

// Scratch (static __device__ — no allocations allowed)
__device__ float g_qkv[3ull * MROWS * NXC];   // [3][MROWS][NXC]
__device__ float g_att[(size_t)MROWS * NXC];  // attention output [b*seq][h*64+d]

__device__ __forceinline__ float to_tf32(float x) {
    unsigned u;
    asm("cvt.rna.tf32.f32 %0, %1;" : "=r"(u) : "f"(x));
    return __uint_as_float(u);
}

__device__ __forceinline__ void mma_tf32(float* d,
    unsigned a0, unsigned a1, unsigned a2, unsigned a3,
    unsigned b0, unsigned b1)
{
    asm volatile(
        "mma.sync.aligned.m16n8k8.row.col.f32.tf32.tf32.f32 "
        "{%0,%1,%2,%3},{%4,%5,%6,%7},{%8,%9},{%0,%1,%2,%3};"
        : "+f"(d[0]), "+f"(d[1]), "+f"(d[2]), "+f"(d[3])
        : "r"(a0), "r"(a1), "r"(a2), "r"(a3), "r"(b0), "r"(b1));
}

#define F2U __float_as_uint

// ---------------------------------------------------------------------------
// tf32 tensor-core GEMM: C[M,N] = A[M,K] @ B[K,N] + bias.
// Block 128x128, BK=16, double-buffered smem, 256 thr = 8 warps (2m x 4n),
// warp tile 64x32 -> 4x4 m16n8k8 mma per 8-k step.
// SPLITOUT=1: scatter cols into g_qkv Q/K/V parts. ATT_IN=1: A := g_att.
// ---------------------------------------------------------------------------
#define ASTR 20    // 16 + 4 pad  (conflict-free A-frag LDS)
#define BSTR 136   // 128 + 8 pad (conflict-free B-frag LDS)

template<int SPLITOUT, int ATT_IN>
__global__ void __launch_bounds__(256, 2)
gemm_tc(const float* __restrict__ A, const float* __restrict__ B,
        const float* __restrict__ bias, float* __restrict__ C,
        int M, int N, int K)
{
    __shared__ float As[2][128 * ASTR];
    __shared__ float Bs[2][16 * BSTR];

    const float* Ap = (ATT_IN == 1) ? g_att : A;

    int tid  = threadIdx.x;
    int lane = tid & 31;
    int w    = tid >> 5;
    int wm   = w & 1;       // 0..1  (64-row slabs)
    int wn   = w >> 1;      // 0..3  (32-col slabs)
    int lq   = lane >> 2;   // 0..7
    int lr   = lane & 3;    // 0..3

    int brow = blockIdx.y * 128;
    int bcol = blockIdx.x * 128;

    // gmem tile-load mapping (2 float4 each for A and B per thread)
    int am0 = tid >> 2;            // A row within tile for f=tid
    int akq = (tid & 3) << 2;      // A k-quad
    int bk0 = tid >> 5;            // B k-row for f=tid  (wait: f/32)
    int bnq = (tid & 31) << 2;     // B n-quad

    float4 ra[2], rb[2];

    float acc[4][4][4];
    #pragma unroll
    for (int mi = 0; mi < 4; mi++)
        #pragma unroll
        for (int ni = 0; ni < 4; ni++)
            #pragma unroll
            for (int j = 0; j < 4; j++) acc[mi][ni][j] = 0.f;

    const int NT = K / 16;

    // --- helpers (macros to keep everything inlined) ---
#define LOADG(t)                                                              \
    {                                                                         \
        int k0 = (t) * 16;                                                    \
        _Pragma("unroll")                                                     \
        for (int i = 0; i < 2; i++) {                                         \
            int f = tid + i * 256;                                            \
            int m = f >> 2, kq = (f & 3) << 2;                                \
            ra[i] = *(const float4*)(Ap + (size_t)(brow + m) * K + k0 + kq);  \
            int kk = f >> 5, nq = (f & 31) << 2;                              \
            rb[i] = *(const float4*)(B + (size_t)(k0 + kk) * N + bcol + nq);  \
        }                                                                     \
    }

#define STORES(buf)                                                           \
    {                                                                         \
        _Pragma("unroll")                                                     \
        for (int i = 0; i < 2; i++) {                                         \
            int f = tid + i * 256;                                            \
            int m = f >> 2, kq = (f & 3) << 2;                                \
            float4 va = make_float4(to_tf32(ra[i].x), to_tf32(ra[i].y),       \
                                    to_tf32(ra[i].z), to_tf32(ra[i].w));      \
            *(float4*)&As[buf][m * ASTR + kq] = va;                           \
            int kk = f >> 5, nq = (f & 31) << 2;                              \
            float4 vb = make_float4(to_tf32(rb[i].x), to_tf32(rb[i].y),       \
                                    to_tf32(rb[i].z), to_tf32(rb[i].w));      \
            *(float4*)&Bs[buf][kk * BSTR + nq] = vb;                          \
        }                                                                     \
    }

#define COMPUTE(buf)                                                          \
    {                                                                         \
        _Pragma("unroll")                                                     \
        for (int ks = 0; ks < 16; ks += 8) {                                  \
            unsigned af[4][4];                                                \
            _Pragma("unroll")                                                 \
            for (int mi = 0; mi < 4; mi++) {                                  \
                int r = (wm * 64 + mi * 16 + lq) * ASTR + ks + lr;            \
                af[mi][0] = F2U(As[buf][r]);                                  \
                af[mi][1] = F2U(As[buf][r + 8 * ASTR]);                       \
                af[mi][2] = F2U(As[buf][r + 4]);                              \
                af[mi][3] = F2U(As[buf][r + 8 * ASTR + 4]);                   \
            }                                                                 \
            _Pragma("unroll")                                                 \
            for (int ni = 0; ni < 4; ni++) {                                  \
                int bx = (ks + lr) * BSTR + wn * 32 + ni * 8 + lq;            \
                unsigned b0 = F2U(Bs[buf][bx]);                               \
                unsigned b1 = F2U(Bs[buf][bx + 4 * BSTR]);                    \
                _Pragma("unroll")                                             \
                for (int mi = 0; mi < 4; mi++)                                \
                    mma_tf32(acc[mi][ni], af[mi][0], af[mi][1],               \
                             af[mi][2], af[mi][3], b0, b1);                   \
            }                                                                 \
        }                                                                     \
    }

    LOADG(0);
    STORES(0);
    __syncthreads();

    for (int t = 0; t < NT; t++) {
        if (t + 1 < NT) LOADG(t + 1);
        COMPUTE(t & 1);
        if (t + 1 < NT) {
            STORES((t + 1) & 1);
            __syncthreads();
        }
    }

    // Epilogue
    #pragma unroll
    for (int mi = 0; mi < 4; mi++) {
        int r0 = brow + wm * 64 + mi * 16 + lq;
        #pragma unroll
        for (int ni = 0; ni < 4; ni++) {
            int col = bcol + wn * 32 + ni * 8 + lr * 2;
            float bv0 = bias[col], bv1 = bias[col + 1];
            float2 v0 = make_float2(acc[mi][ni][0] + bv0, acc[mi][ni][1] + bv1);
            float2 v1 = make_float2(acc[mi][ni][2] + bv0, acc[mi][ni][3] + bv1);
            if (SPLITOUT == 0) {
                *(float2*)(C + (size_t)r0 * N + col) = v0;
                *(float2*)(C + (size_t)(r0 + 8) * N + col) = v1;
            } else {
                int part = col / NXC;
                int c = col - part * NXC;
                float* dst = g_qkv + (size_t)part * MROWS * NXC + c;
                *(float2*)(dst + (size_t)r0 * NXC) = v0;
                *(float2*)(dst + (size_t)(r0 + 8) * NXC) = v1;
            }
        }
    }
#undef LOADG
#undef STORES
#undef COMPUTE
}

// ---------------------------------------------------------------------------
// Flash attention with tf32 mma. One block per (qb, head, batch):
// 64 q-rows x 64 k-cols, 128 threads = 4 warps, warp = 16 q-rows.
// S = Q@K^T via m16n8k8 (K tile needs NO transpose: row.col form).
// P round-trips through smem as tf32 A-fragments; V stored transposed.
// smem: Qs,Ks,Vs,Ps each 64x72 fp32 -> 73728 B dynamic.
// ---------------------------------------------------------------------------
#define AST 72   // 64 + 8 pad: conflict-free fragment LDS

__global__ void attn_kernel(const float* __restrict__ amask)
{
    extern __shared__ float sm[];
    float* Qs = sm;                  // [row][d]
    float* Ks = Qs + 64 * AST;       // [kcol][d]
    float* Vs = Ks + 64 * AST;       // [d][kseq]  (transposed)
    float* Ps = Vs + 64 * AST;       // [row][kseq]

    int b  = blockIdx.z;
    int h  = blockIdx.y;
    int qb = gridDim.x - 1 - blockIdx.x;  // heavy blocks first
    int tid  = threadIdx.x;
    int lane = tid & 31;
    int w    = tid >> 5;
    int lq   = lane >> 2;
    int lr   = lane & 3;

    const size_t bh = (size_t)b * SEQ * NXC + (size_t)h * SEQ * HD;
    const float* Qg = g_qkv + bh;
    const float* Kg = g_qkv + (size_t)MROWS * NXC + bh;
    const float* Vg = g_qkv + 2ull * MROWS * NXC + bh;
    const float* am = amask + (size_t)b * SEQ;

    // Load Q tile (cvt to tf32)
    #pragma unroll
    for (int it = 0; it < 8; it++) {
        int f = tid + it * 128;           // float4 index 0..1023
        int r = f >> 4;
        int dq = (f & 15) << 2;
        float4 v = *(const float4*)(Qg + (size_t)(qb * 64 + r) * HD + dq);
        *(float4*)&Qs[r * AST + dq] = make_float4(to_tf32(v.x), to_tf32(v.y),
                                                  to_tf32(v.z), to_tf32(v.w));
    }

    float o[8][4];
    #pragma unroll
    for (int ni = 0; ni < 8; ni++)
        #pragma unroll
        for (int j = 0; j < 4; j++) o[ni][j] = 0.f;
    float m0 = -INFINITY, m1 = -INFINITY, l0 = 0.f, l1 = 0.f;

    int arow0 = (w * 16 + lq) * AST;
    int arow1 = arow0 + 8 * AST;

    for (int kb = 0; kb <= qb; kb++) {
        __syncthreads();   // prior iter's reads of Ks/Vs/Ps complete
        #pragma unroll
        for (int it = 0; it < 8; it++) {
            int f = tid + it * 128;
            int r = f >> 4;
            int dq = (f & 15) << 2;
            float4 kv = *(const float4*)(Kg + (size_t)(kb * 64 + r) * HD + dq);
            *(float4*)&Ks[r * AST + dq] = make_float4(to_tf32(kv.x), to_tf32(kv.y),
                                                      to_tf32(kv.z), to_tf32(kv.w));
            float4 vv = *(const float4*)(Vg + (size_t)(kb * 64 + r) * HD + dq);
            Vs[(dq + 0) * AST + r] = to_tf32(vv.x);
            Vs[(dq + 1) * AST + r] = to_tf32(vv.y);
            Vs[(dq + 2) * AST + r] = to_tf32(vv.z);
            Vs[(dq + 3) * AST + r] = to_tf32(vv.w);
        }
        __syncthreads();

        // ---- S = Q @ K^T ----
        float s[8][4];
        #pragma unroll
        for (int ni = 0; ni < 8; ni++)
            #pragma unroll
            for (int j = 0; j < 4; j++) s[ni][j] = 0.f;

        #pragma unroll
        for (int ks = 0; ks < 8; ks++) {
            int ka = ks * 8 + lr;
            unsigned a0 = F2U(Qs[arow0 + ka]);
            unsigned a1 = F2U(Qs[arow1 + ka]);
            unsigned a2 = F2U(Qs[arow0 + ka + 4]);
            unsigned a3 = F2U(Qs[arow1 + ka + 4]);
            #pragma unroll
            for (int ni = 0; ni < 8; ni++) {
                int bx = (ni * 8 + lq) * AST + ka;
                mma_tf32(s[ni], a0, a1, a2, a3, F2U(Ks[bx]), F2U(Ks[bx + 4]));
            }
        }

        // ---- scale + causal mask + attention_mask ----
        int grow0 = qb * 64 + w * 16 + lq;
        int grow1 = grow0 + 8;
        float rm0 = -INFINITY, rm1 = -INFINITY;
        #pragma unroll
        for (int ni = 0; ni < 8; ni++) {
            #pragma unroll
            for (int c = 0; c < 2; c++) {
                int gcol = kb * 64 + ni * 8 + lr * 2 + c;
                float amv = am[gcol];
                float v = s[ni][c] * 0.125f;
                if (gcol > grow0) v = -10000.0f;
                v += amv;
                s[ni][c] = v;
                rm0 = fmaxf(rm0, v);
                float v2 = s[ni][2 + c] * 0.125f;
                if (gcol > grow1) v2 = -10000.0f;
                v2 += amv;
                s[ni][2 + c] = v2;
                rm1 = fmaxf(rm1, v2);
            }
        }
        #pragma unroll
        for (int off = 1; off <= 2; off <<= 1) {
            rm0 = fmaxf(rm0, __shfl_xor_sync(0xffffffffu, rm0, off));
            rm1 = fmaxf(rm1, __shfl_xor_sync(0xffffffffu, rm1, off));
        }
        float mn0 = fmaxf(m0, rm0), mn1 = fmaxf(m1, rm1);
        float al0 = __expf(m0 - mn0), al1 = __expf(m1 - mn1);
        float rs0 = 0.f, rs1 = 0.f;
        #pragma unroll
        for (int ni = 0; ni < 8; ni++) {
            #pragma unroll
            for (int c = 0; c < 2; c++) {
                s[ni][c]     = __expf(s[ni][c] - mn0);     rs0 += s[ni][c];
                s[ni][2 + c] = __expf(s[ni][2 + c] - mn1); rs1 += s[ni][2 + c];
            }
        }
        #pragma unroll
        for (int off = 1; off <= 2; off <<= 1) {
            rs0 += __shfl_xor_sync(0xffffffffu, rs0, off);
            rs1 += __shfl_xor_sync(0xffffffffu, rs1, off);
        }
        l0 = l0 * al0 + rs0; m0 = mn0;
        l1 = l1 * al1 + rs1; m1 = mn1;
        #pragma unroll
        for (int ni = 0; ni < 8; ni++) {
            o[ni][0] *= al0; o[ni][1] *= al0;
            o[ni][2] *= al1; o[ni][3] *= al1;
        }

        // ---- store P (tf32) to smem as A-fragments ----
        #pragma unroll
        for (int ni = 0; ni < 8; ni++) {
            int c0 = ni * 8 + lr * 2;
            Ps[arow0 + c0]     = to_tf32(s[ni][0]);
            Ps[arow0 + c0 + 1] = to_tf32(s[ni][1]);
            Ps[arow1 + c0]     = to_tf32(s[ni][2]);
            Ps[arow1 + c0 + 1] = to_tf32(s[ni][3]);
        }
        __syncthreads();

        // ---- O += P @ V ----
        #pragma unroll
        for (int ks = 0; ks < 8; ks++) {
            int ka = ks * 8 + lr;
            unsigned a0 = F2U(Ps[arow0 + ka]);
            unsigned a1 = F2U(Ps[arow1 + ka]);
            unsigned a2 = F2U(Ps[arow0 + ka + 4]);
            unsigned a3 = F2U(Ps[arow1 + ka + 4]);
            #pragma unroll
            for (int ni = 0; ni < 8; ni++) {
                int bx = (ni * 8 + lq) * AST + ka;
                mma_tf32(o[ni], a0, a1, a2, a3, F2U(Vs[bx]), F2U(Vs[bx + 4]));
            }
        }
    }

    // Epilogue: O / l -> g_att[b*SEQ+row][h*64+d]
    float inv0 = 1.0f / l0, inv1 = 1.0f / l1;
    int r0 = qb * 64 + w * 16 + lq;
    #pragma unroll
    for (int ni = 0; ni < 8; ni++) {
        int d = h * HD + ni * 8 + lr * 2;
        float* dst0 = g_att + ((size_t)b * SEQ + r0) * NXC + d;
        *(float2*)dst0 = make_float2(o[ni][0] * inv0, o[ni][1] * inv0);
        float* dst1 = g_att + ((size_t)b * SEQ + r0 + 8) * NXC + d;
        *(float2*)dst1 = make_float2(o[ni][2] * inv1, o[ni][3] * inv1);
    }
}

extern "C" void kernel_launch(void* const* d_in, const int* in_sizes, int n_in,
                              void* d_out, int out_size)
{
    const float* x      = (const float*)d_in[0];  // [2,2048,768]
    const float* amask  = (const float*)d_in[1];  // [2,1,1,2048]
    const float* w_attn = (const float*)d_in[2];  // [768,2304]
    const float* b_attn = (const float*)d_in[3];  // [2304]
    const float* w_proj = (const float*)d_in[4];  // [768,768]
    const float* b_proj = (const float*)d_in[5];  // [768]
    float* out = (float*)d_out;                   // [2,2048,768]

    // 1) QKV projection -> g_qkv split
    gemm_tc<1, 0><<<dim3(QKVN / 128, MROWS / 128), 256>>>(
        x, w_attn, b_attn, nullptr, MROWS, QKVN, NXC);

    // 2) Flash attention (73.7 KB dynamic smem)
    cudaFuncSetAttribute(attn_kernel,
                         cudaFuncAttributeMaxDynamicSharedMemorySize, 73728);
    attn_kernel<<<dim3(SEQ / 64, NH, BSZ), 128, 73728>>>(amask);

    // 3) Output projection -> d_out
    gemm_tc<0, 1><<<dim3(NXC / 128, MROWS / 128), 256>>>(
        nullptr, w_proj, b_proj, out, MROWS, NXC, NXC);
}

// round 6
// speedup vs baseline: 3.5591x; 1.5703x over previous
#include <cuda_runtime.h>
#include <math.h>

#define SEQ   2048
#define NXC   768
#define NH    12
#define HD    64
#define BSZ   2
#define MROWS (BSZ*SEQ)      // 4096
#define QKVN  (3*NXC)        // 2304

// Scratch (static __device__ — no allocations allowed)
__device__ float g_qkv[3ull * MROWS * NXC];   // [3][MROWS][NXC], tf32-rounded
__device__ float g_att[(size_t)MROWS * NXC];  // attn out [b*seq][h*64+d], tf32-rounded
__device__ float g_x [(size_t)MROWS * NXC];   // tf32-rounded hidden_states
__device__ float g_wa[(size_t)NXC * QKVN];    // tf32-rounded w_attn
__device__ float g_wp[(size_t)NXC * NXC];     // tf32-rounded w_proj

__device__ __forceinline__ float to_tf32(float x) {
    unsigned u;
    asm("cvt.rna.tf32.f32 %0, %1;" : "=r"(u) : "f"(x));
    return __uint_as_float(u);
}

__device__ __forceinline__ void mma_tf32(float* d,
    unsigned a0, unsigned a1, unsigned a2, unsigned a3,
    unsigned b0, unsigned b1)
{
    asm volatile(
        "mma.sync.aligned.m16n8k8.row.col.f32.tf32.tf32.f32 "
        "{%0,%1,%2,%3},{%4,%5,%6,%7},{%8,%9},{%0,%1,%2,%3};"
        : "+f"(d[0]), "+f"(d[1]), "+f"(d[2]), "+f"(d[3])
        : "r"(a0), "r"(a1), "r"(a2), "r"(a3), "r"(b0), "r"(b1));
}

#define F2U __float_as_uint

__device__ __forceinline__ void cp16(unsigned dst, const void* src) {
    asm volatile("cp.async.cg.shared.global [%0], [%1], 16;"
                 :: "r"(dst), "l"(src));
}
#define CP_COMMIT()  asm volatile("cp.async.commit_group;")
#define CP_WAIT(n)   asm volatile("cp.async.wait_group " #n ";")
__device__ __forceinline__ unsigned smem_u32(const void* p) {
    return (unsigned)__cvta_generic_to_shared(p);
}

// ---------------------------------------------------------------------------
// Elementwise tf32 rounding (pre-pass for x, w_attn, w_proj)
// ---------------------------------------------------------------------------
__global__ void cvt_tf32_kernel(const float4* __restrict__ src,
                                float4* __restrict__ dst, int n4)
{
    int i = blockIdx.x * blockDim.x + threadIdx.x;
    if (i < n4) {
        float4 v = src[i];
        dst[i] = make_float4(to_tf32(v.x), to_tf32(v.y), to_tf32(v.z), to_tf32(v.w));
    }
}

// ---------------------------------------------------------------------------
// tf32 GEMM, 3-stage cp.async pipeline. C[M,N] = A@B + bias.
// Block 128x128, BK=16, 256 thr = 8 warps (2m x 4n), warp tile 64x32.
// Inputs already tf32-rounded. SPLITOUT: scatter into g_qkv. ROUND: round out.
// ---------------------------------------------------------------------------
#define ASTR 20
#define BSTR 136
#define GSTAGE_A (128*ASTR)
#define GSTAGE_B (16*BSTR)

template<int SPLITOUT, int ROUND>
__global__ void __launch_bounds__(256, 2)
gemm_tc(const float* __restrict__ A, const float* __restrict__ B,
        const float* __restrict__ bias, float* __restrict__ C,
        int M, int N, int K)
{
    extern __shared__ float sg[];
    float* As = sg;                     // [3][128*ASTR]
    float* Bs = sg + 3 * GSTAGE_A;      // [3][16*BSTR]

    int tid  = threadIdx.x;
    int lane = tid & 31;
    int w    = tid >> 5;
    int wm   = w & 1;
    int wn   = w >> 1;
    int lq   = lane >> 2;
    int lr   = lane & 3;

    int brow = blockIdx.y * 128;
    int bcol = blockIdx.x * 128;

    float acc[4][4][4];
    #pragma unroll
    for (int mi = 0; mi < 4; mi++)
        #pragma unroll
        for (int ni = 0; ni < 4; ni++)
            #pragma unroll
            for (int j = 0; j < 4; j++) acc[mi][ni][j] = 0.f;

    const int NT = K / 16;

    auto issue = [&](int t, int s) {
        int k0 = t * 16;
        float* as = As + s * GSTAGE_A;
        float* bs = Bs + s * GSTAGE_B;
        #pragma unroll
        for (int i = 0; i < 2; i++) {
            int f = tid + i * 256;
            int m = f >> 2, cq = (f & 3) << 2;
            cp16(smem_u32(&as[m * ASTR + cq]),
                 A + (size_t)(brow + m) * K + k0 + cq);
            int kr = f >> 5, nq = (f & 31) << 2;
            cp16(smem_u32(&bs[kr * BSTR + nq]),
                 B + (size_t)(k0 + kr) * N + bcol + nq);
        }
        CP_COMMIT();
    };

    issue(0, 0);
    issue(1, 1);

    for (int t = 0; t < NT; t++) {
        CP_WAIT(1);
        __syncthreads();
        if (t + 2 < NT) issue(t + 2, (t + 2) % 3);

        const float* as = As + (t % 3) * GSTAGE_A;
        const float* bs = Bs + (t % 3) * GSTAGE_B;
        #pragma unroll
        for (int ks = 0; ks < 16; ks += 8) {
            unsigned af[4][4];
            #pragma unroll
            for (int mi = 0; mi < 4; mi++) {
                int r = (wm * 64 + mi * 16 + lq) * ASTR + ks + lr;
                af[mi][0] = F2U(as[r]);
                af[mi][1] = F2U(as[r + 8 * ASTR]);
                af[mi][2] = F2U(as[r + 4]);
                af[mi][3] = F2U(as[r + 8 * ASTR + 4]);
            }
            #pragma unroll
            for (int ni = 0; ni < 4; ni++) {
                int bx = (ks + lr) * BSTR + wn * 32 + ni * 8 + lq;
                unsigned b0 = F2U(bs[bx]);
                unsigned b1 = F2U(bs[bx + 4 * BSTR]);
                #pragma unroll
                for (int mi = 0; mi < 4; mi++)
                    mma_tf32(acc[mi][ni], af[mi][0], af[mi][1],
                             af[mi][2], af[mi][3], b0, b1);
            }
        }
    }

    // Epilogue
    #pragma unroll
    for (int mi = 0; mi < 4; mi++) {
        int r0 = brow + wm * 64 + mi * 16 + lq;
        #pragma unroll
        for (int ni = 0; ni < 4; ni++) {
            int col = bcol + wn * 32 + ni * 8 + lr * 2;
            float bv0 = bias[col], bv1 = bias[col + 1];
            float v00 = acc[mi][ni][0] + bv0, v01 = acc[mi][ni][1] + bv1;
            float v10 = acc[mi][ni][2] + bv0, v11 = acc[mi][ni][3] + bv1;
            if (ROUND) {
                v00 = to_tf32(v00); v01 = to_tf32(v01);
                v10 = to_tf32(v10); v11 = to_tf32(v11);
            }
            if (SPLITOUT == 0) {
                *(float2*)(C + (size_t)r0 * N + col) = make_float2(v00, v01);
                *(float2*)(C + (size_t)(r0 + 8) * N + col) = make_float2(v10, v11);
            } else {
                int part = col / NXC;
                int c = col - part * NXC;
                float* dst = g_qkv + (size_t)part * MROWS * NXC + c;
                *(float2*)(dst + (size_t)r0 * NXC) = make_float2(v00, v01);
                *(float2*)(dst + (size_t)(r0 + 8) * NXC) = make_float2(v10, v11);
            }
        }
    }
}

// ---------------------------------------------------------------------------
// Flash attention, tf32 mma. Block = 128 q-rows x (all keys), tiles of 64 keys.
// 256 thr = 8 warps x 16 q-rows. Q frags persistent in regs. K/V double-
// buffered via cp.async. P stays in registers: the S-accumulator fragment is
// reused directly as the PV A-fragment with a permuted V k-index
// (b0 -> key 2*lr, b1 -> key 2*lr+1).  smem = 4 x 64 x 68 floats = 69.6 KB.
// ---------------------------------------------------------------------------
#define VAST 68
#define KVSTG (64*VAST)

__global__ void __launch_bounds__(256, 2) attn_kernel(const float* __restrict__ amask)
{
    extern __shared__ float kv[];   // [4][64*VAST]: buf0K, buf0V, buf1K, buf1V

    int b  = blockIdx.z;
    int h  = blockIdx.y;
    int qb = 15 - blockIdx.x;       // heavy blocks first (gridDim.x == 16)
    int tid  = threadIdx.x;
    int lane = tid & 31;
    int w    = tid >> 5;
    int lq   = lane >> 2;
    int lr   = lane & 3;
    int r0   = qb * 128;

    const size_t bh = (size_t)b * SEQ * NXC + (size_t)h * SEQ * HD;
    const float* Qg = g_qkv + bh;
    const float* Kg = g_qkv + (size_t)MROWS * NXC + bh;
    const float* Vg = g_qkv + 2ull * MROWS * NXC + bh;
    const float* am = amask + (size_t)b * SEQ;

    // Persistent Q fragments (values already tf32-rounded in g_qkv)
    int qrow = r0 + w * 16 + lq;
    unsigned qa[8][4];
    #pragma unroll
    for (int ks = 0; ks < 8; ks++) {
        qa[ks][0] = F2U(Qg[(size_t)qrow * HD + ks * 8 + lr]);
        qa[ks][1] = F2U(Qg[(size_t)(qrow + 8) * HD + ks * 8 + lr]);
        qa[ks][2] = F2U(Qg[(size_t)qrow * HD + ks * 8 + lr + 4]);
        qa[ks][3] = F2U(Qg[(size_t)(qrow + 8) * HD + ks * 8 + lr + 4]);
    }

    float o[8][4];
    #pragma unroll
    for (int dj = 0; dj < 8; dj++)
        #pragma unroll
        for (int j = 0; j < 4; j++) o[dj][j] = 0.f;
    float m0 = -INFINITY, m1 = -INFINITY, l0 = 0.f, l1 = 0.f;

    const int nkb = 2 * qb + 2;

    auto issue = [&](int kb) {
        float* kd = kv + (kb & 1) * 2 * KVSTG;
        float* vd = kd + KVSTG;
        const float* ks_g = Kg + (size_t)kb * 64 * HD;
        const float* vs_g = Vg + (size_t)kb * 64 * HD;
        #pragma unroll
        for (int i = 0; i < 4; i++) {
            int f = tid + i * 256;          // 0..1023 float4 slots
            int r = f >> 4, cq = (f & 15) << 2;
            cp16(smem_u32(&kd[r * VAST + cq]), ks_g + (size_t)r * HD + cq);
            cp16(smem_u32(&vd[r * VAST + cq]), vs_g + (size_t)r * HD + cq);
        }
        CP_COMMIT();
    };

    issue(0);

    for (int kb = 0; kb < nkb; kb++) {
        if (kb + 1 < nkb) issue(kb + 1);
        CP_WAIT(1);
        __syncthreads();

        const float* Ks = kv + (kb & 1) * 2 * KVSTG;
        const float* Vs = Ks + KVSTG;

        // ---- S = Q @ K^T ----
        float s[8][4];
        #pragma unroll
        for (int ni = 0; ni < 8; ni++)
            #pragma unroll
            for (int j = 0; j < 4; j++) s[ni][j] = 0.f;

        #pragma unroll
        for (int ks = 0; ks < 8; ks++) {
            #pragma unroll
            for (int ni = 0; ni < 8; ni++) {
                int bx = (ni * 8 + lq) * VAST + ks * 8 + lr;
                mma_tf32(s[ni], qa[ks][0], qa[ks][1], qa[ks][2], qa[ks][3],
                         F2U(Ks[bx]), F2U(Ks[bx + 4]));
            }
        }

        // ---- scale + causal mask + attention_mask + row max ----
        bool need_mask = (kb >= 2 * qb);
        float rm0 = -INFINITY, rm1 = -INFINITY;
        #pragma unroll
        for (int ni = 0; ni < 8; ni++) {
            int gc0 = kb * 64 + ni * 8 + 2 * lr;
            float2 amv = *(const float2*)(am + gc0);
            float v00 = s[ni][0] * 0.125f, v01 = s[ni][1] * 0.125f;
            float v10 = s[ni][2] * 0.125f, v11 = s[ni][3] * 0.125f;
            if (need_mask) {
                if (gc0     > qrow)     v00 = -10000.f;
                if (gc0 + 1 > qrow)     v01 = -10000.f;
                if (gc0     > qrow + 8) v10 = -10000.f;
                if (gc0 + 1 > qrow + 8) v11 = -10000.f;
            }
            v00 += amv.x; v01 += amv.y; v10 += amv.x; v11 += amv.y;
            s[ni][0] = v00; s[ni][1] = v01; s[ni][2] = v10; s[ni][3] = v11;
            rm0 = fmaxf(rm0, fmaxf(v00, v01));
            rm1 = fmaxf(rm1, fmaxf(v10, v11));
        }
        #pragma unroll
        for (int off = 1; off <= 2; off <<= 1) {
            rm0 = fmaxf(rm0, __shfl_xor_sync(0xffffffffu, rm0, off));
            rm1 = fmaxf(rm1, __shfl_xor_sync(0xffffffffu, rm1, off));
        }

        // ---- online softmax ----
        float mn0 = fmaxf(m0, rm0), mn1 = fmaxf(m1, rm1);
        float al0 = __expf(m0 - mn0), al1 = __expf(m1 - mn1);
        float rs0 = 0.f, rs1 = 0.f;
        #pragma unroll
        for (int ni = 0; ni < 8; ni++) {
            s[ni][0] = __expf(s[ni][0] - mn0);
            s[ni][1] = __expf(s[ni][1] - mn0);
            s[ni][2] = __expf(s[ni][2] - mn1);
            s[ni][3] = __expf(s[ni][3] - mn1);
            rs0 += s[ni][0] + s[ni][1];
            rs1 += s[ni][2] + s[ni][3];
        }
        #pragma unroll
        for (int off = 1; off <= 2; off <<= 1) {
            rs0 += __shfl_xor_sync(0xffffffffu, rs0, off);
            rs1 += __shfl_xor_sync(0xffffffffu, rs1, off);
        }
        l0 = l0 * al0 + rs0; m0 = mn0;
        l1 = l1 * al1 + rs1; m1 = mn1;
        #pragma unroll
        for (int dj = 0; dj < 8; dj++) {
            o[dj][0] *= al0; o[dj][1] *= al0;
            o[dj][2] *= al1; o[dj][3] *= al1;
        }

        // ---- O += P @ V  (P = S-accum reused as A-frag; V k-index permuted) ----
        #pragma unroll
        for (int ni = 0; ni < 8; ni++) {
            unsigned a0, a1, a2, a3;
            asm("cvt.rna.tf32.f32 %0, %1;" : "=r"(a0) : "f"(s[ni][0]));
            asm("cvt.rna.tf32.f32 %0, %1;" : "=r"(a1) : "f"(s[ni][2]));
            asm("cvt.rna.tf32.f32 %0, %1;" : "=r"(a2) : "f"(s[ni][1]));
            asm("cvt.rna.tf32.f32 %0, %1;" : "=r"(a3) : "f"(s[ni][3]));
            int vrow = (ni * 8 + 2 * lr) * VAST;
            #pragma unroll
            for (int dj = 0; dj < 8; dj++) {
                int bx = vrow + dj * 8 + lq;
                mma_tf32(o[dj], a0, a1, a2, a3,
                         F2U(Vs[bx]), F2U(Vs[bx + VAST]));
            }
        }
        __syncthreads();   // all warps done with this buffer before it refills
    }

    // Epilogue: O / l -> g_att (tf32-rounded for the proj GEMM)
    float inv0 = 1.0f / l0, inv1 = 1.0f / l1;
    #pragma unroll
    for (int dj = 0; dj < 8; dj++) {
        int d = h * HD + dj * 8 + 2 * lr;
        float* dst0 = g_att + ((size_t)b * SEQ + qrow) * NXC + d;
        *(float2*)dst0 = make_float2(to_tf32(o[dj][0] * inv0),
                                     to_tf32(o[dj][1] * inv0));
        float* dst1 = g_att + ((size_t)b * SEQ + qrow + 8) * NXC + d;
        *(float2*)dst1 = make_float2(to_tf32(o[dj][2] * inv1),
                                     to_tf32(o[dj][3] * inv1));
    }
}

extern "C" void kernel_launch(void* const* d_in, const int* in_sizes, int n_in,
                              void* d_out, int out_size)
{
    const float* x      = (const float*)d_in[0];
    const float* amask  = (const float*)d_in[1];
    const float* w_attn = (const float*)d_in[2];
    const float* b_attn = (const float*)d_in[3];
    const float* w_proj = (const float*)d_in[4];
    const float* b_proj = (const float*)d_in[5];
    float* out = (float*)d_out;

    // Device addresses of __device__ symbols (host-side symbol use is invalid;
    // with ATS it silently reads host memory — round-4 bug).
    float *gx, *gwa, *gwp, *gatt;
    cudaGetSymbolAddress((void**)&gx,   g_x);
    cudaGetSymbolAddress((void**)&gwa,  g_wa);
    cudaGetSymbolAddress((void**)&gwp,  g_wp);
    cudaGetSymbolAddress((void**)&gatt, g_att);

    // 0) tf32-round inputs once (RNA), so GEMMs can cp.async raw
    {
        int n4x = MROWS * NXC / 4, n4a = NXC * QKVN / 4, n4p = NXC * NXC / 4;
        cvt_tf32_kernel<<<(n4x + 255) / 256, 256>>>((const float4*)x, (float4*)gx, n4x);
        cvt_tf32_kernel<<<(n4a + 255) / 256, 256>>>((const float4*)w_attn, (float4*)gwa, n4a);
        cvt_tf32_kernel<<<(n4p + 255) / 256, 256>>>((const float4*)w_proj, (float4*)gwp, n4p);
    }

    const int gsmem = (3 * GSTAGE_A + 3 * GSTAGE_B) * 4;   // 56,832 B
    cudaFuncSetAttribute(gemm_tc<1, 1>,
                         cudaFuncAttributeMaxDynamicSharedMemorySize, gsmem);
    cudaFuncSetAttribute(gemm_tc<0, 0>,
                         cudaFuncAttributeMaxDynamicSharedMemorySize, gsmem);
    cudaFuncSetAttribute(attn_kernel,
                         cudaFuncAttributeMaxDynamicSharedMemorySize, 4 * KVSTG * 4);

    // 1) QKV projection -> g_qkv (tf32-rounded split)
    gemm_tc<1, 1><<<dim3(QKVN / 128, MROWS / 128), 256, gsmem>>>(
        gx, gwa, b_attn, nullptr, MROWS, QKVN, NXC);

    // 2) Flash attention (69.6 KB dynamic smem)
    attn_kernel<<<dim3(SEQ / 128, NH, BSZ), 256, 4 * KVSTG * 4>>>(amask);

    // 3) Output projection -> d_out (exact fp32 out)
    gemm_tc<0, 0><<<dim3(NXC / 128, MROWS / 128), 256, gsmem>>>(
        gatt, gwp, b_proj, out, MROWS, NXC, NXC);
}

// round 8
// speedup vs baseline: 3.9639x; 1.1137x over previous
#include <cuda_runtime.h>
#include <math.h>

#define SEQ   2048
#define NXC   768
#define NH    12
#define HD    64
#define BSZ   2
#define MROWS (BSZ*SEQ)      // 4096
#define QKVN  (3*NXC)        // 2304

// Scratch (static __device__ — no allocations allowed)
__device__ float g_qkv[3ull * MROWS * NXC];   // [3][MROWS][NXC], tf32-rounded, row-major
__device__ float g_att[(size_t)MROWS * NXC];  // attn out, A-FRAGMENT layout [k8][m16][lane][4]
__device__ float g_x [(size_t)MROWS * NXC];   // x, A-frag layout [k8][m16][lane][4]
__device__ float g_wa[(size_t)NXC * QKVN];    // w_attn, B-frag layout [k8][n8][lane][2]
__device__ float g_wp[(size_t)NXC * NXC];     // w_proj, B-frag layout

__device__ __forceinline__ float to_tf32(float x) {
    unsigned u;
    asm("cvt.rna.tf32.f32 %0, %1;" : "=r"(u) : "f"(x));
    return __uint_as_float(u);
}

__device__ __forceinline__ void mma_tf32(float* d,
    unsigned a0, unsigned a1, unsigned a2, unsigned a3,
    unsigned b0, unsigned b1)
{
    asm volatile(
        "mma.sync.aligned.m16n8k8.row.col.f32.tf32.tf32.f32 "
        "{%0,%1,%2,%3},{%4,%5,%6,%7},{%8,%9},{%0,%1,%2,%3};"
        : "+f"(d[0]), "+f"(d[1]), "+f"(d[2]), "+f"(d[3])
        : "r"(a0), "r"(a1), "r"(a2), "r"(a3), "r"(b0), "r"(b1));
}

#define F2U __float_as_uint

__device__ __forceinline__ void cp16(unsigned dst, const void* src) {
    asm volatile("cp.async.cg.shared.global [%0], [%1], 16;"
                 :: "r"(dst), "l"(src));
}
#define CP_COMMIT()  asm volatile("cp.async.commit_group;")
#define CP_WAIT(n)   asm volatile("cp.async.wait_group " #n ";")
__device__ __forceinline__ unsigned smem_u32(const void* p) {
    return (unsigned)__cvta_generic_to_shared(p);
}

// ---------------------------------------------------------------------------
// Pack kernels: tf32-round AND permute into mma fragment order.
// A-frag (m16n8k8): reg0=(lq,lr) reg1=(lq+8,lr) reg2=(lq,lr+4) reg3=(lq+8,lr+4)
// B-frag:           reg0=B[k=lr][n=lq]  reg1=B[k=lr+4][n=lq]
// ---------------------------------------------------------------------------
__global__ void packA_kernel(const float* __restrict__ src, float* __restrict__ dst,
                             int M, int K)
{
    int idx = blockIdx.x * blockDim.x + threadIdx.x;   // one per [kb][mg][lane]
    int lane = idx & 31;
    int mg   = (idx >> 5) & ((M / 16) - 1);            // M/16 is power-of-2 (256)
    int kb   = idx / (32 * (M / 16));
    if (kb >= K / 8) return;
    int lq = lane >> 2, lr = lane & 3;
    const float* s = src + (size_t)(mg * 16 + lq) * K + kb * 8 + lr;
    float4 v;
    v.x = to_tf32(s[0]);
    v.y = to_tf32(s[8 * K]);
    v.z = to_tf32(s[4]);
    v.w = to_tf32(s[8 * K + 4]);
    ((float4*)dst)[idx] = v;
}

__global__ void packB_kernel(const float* __restrict__ src, float* __restrict__ dst,
                             int K, int N)
{
    int idx = blockIdx.x * blockDim.x + threadIdx.x;   // one per [kb][ng][lane]
    int lane = idx & 31;
    int ng   = (idx >> 5) % (N / 8);
    int kb   = idx / (32 * (N / 8));
    if (kb >= K / 8) return;
    int lq = lane >> 2, lr = lane & 3;
    const float* s = src + (size_t)(kb * 8 + lr) * N + ng * 8 + lq;
    float2 v;
    v.x = to_tf32(s[0]);
    v.y = to_tf32(s[4 * N]);
    ((float2*)dst)[idx] = v;
}

// ---------------------------------------------------------------------------
// tf32 GEMM on fragment-packed operands. C[M,N] = A@B + bias.
// Block 128x128, BK=16 (two k8 slabs/stage), 3-stage cp.async, 256 thr =
// 8 warps (2m x 4n), warp tile 64x32. Per k8: 4 LDS.128 + 4 LDS.64 + 16 mma.
// SPLITOUT: scatter output cols into g_qkv parts. ROUND: tf32-round output.
// ---------------------------------------------------------------------------
#define GSTG 2048   // floats per stage per operand (2 slabs x 1024)

template<int SPLITOUT, int ROUND>
__global__ void __launch_bounds__(256, 2)
gemm_tc(const float* __restrict__ A, const float* __restrict__ B,
        const float* __restrict__ bias, float* __restrict__ C,
        int M, int N, int K)
{
    extern __shared__ float sg[];
    float* As = sg;                 // [3][GSTG]
    float* Bs = sg + 3 * GSTG;      // [3][GSTG]

    int tid  = threadIdx.x;
    int lane = tid & 31;
    int w    = tid >> 5;
    int wm   = w & 1;
    int wn   = w >> 1;
    int lq   = lane >> 2;
    int lr   = lane & 3;

    int brow16 = blockIdx.y * 8;    // m16 base
    int bcol8  = blockIdx.x * 16;   // n8 base
    const int M16 = M / 16, N8 = N / 8;

    float acc[4][4][4];
    #pragma unroll
    for (int mi = 0; mi < 4; mi++)
        #pragma unroll
        for (int ni = 0; ni < 4; ni++)
            #pragma unroll
            for (int j = 0; j < 4; j++) acc[mi][ni][j] = 0.f;

    const int NT = K / 16;

    auto issue = [&](int t, int s) {
        float* as = As + s * GSTG;
        float* bs = Bs + s * GSTG;
        const float* gA = A + ((size_t)(2 * t) * M16 + brow16) * 128 + tid * 4;
        const float* gB = B + ((size_t)(2 * t) * N8  + bcol8) * 64  + tid * 4;
        cp16(smem_u32(as + tid * 4),        gA);
        cp16(smem_u32(as + 1024 + tid * 4), gA + (size_t)M16 * 128);
        cp16(smem_u32(bs + tid * 4),        gB);
        cp16(smem_u32(bs + 1024 + tid * 4), gB + (size_t)N8 * 64);
        CP_COMMIT();
    };

    issue(0, 0);
    issue(1, 1);

    for (int t = 0; t < NT; t++) {
        CP_WAIT(1);
        __syncthreads();
        if (t + 2 < NT) issue(t + 2, (t + 2) % 3);

        // Warp wn owns cols [wn*32, wn*32+32) = n8 groups wn*4..wn*4+3
        //   -> base offset wn*4*64 = wn*256 floats (round-7 bug: was wn*128).
        const float* as0 = As + (t % 3) * GSTG + wm * 512 + lane * 4;
        const float* bs0 = Bs + (t % 3) * GSTG + wn * 256 + lane * 2;
        #pragma unroll
        for (int kk = 0; kk < 2; kk++) {
            const float* as = as0 + kk * 1024;
            const float* bs = bs0 + kk * 1024;
            float4 af[4];
            #pragma unroll
            for (int mi = 0; mi < 4; mi++)
                af[mi] = *(const float4*)(as + mi * 128);
            #pragma unroll
            for (int ni = 0; ni < 4; ni++) {
                float2 bf = *(const float2*)(bs + ni * 64);
                #pragma unroll
                for (int mi = 0; mi < 4; mi++)
                    mma_tf32(acc[mi][ni],
                             F2U(af[mi].x), F2U(af[mi].y),
                             F2U(af[mi].z), F2U(af[mi].w),
                             F2U(bf.x), F2U(bf.y));
            }
        }
    }

    // Epilogue (fragment ownership identical to previous rounds)
    #pragma unroll
    for (int mi = 0; mi < 4; mi++) {
        int r0 = brow16 * 16 + wm * 64 + mi * 16 + lq;
        #pragma unroll
        for (int ni = 0; ni < 4; ni++) {
            int col = bcol8 * 8 + wn * 32 + ni * 8 + lr * 2;
            float bv0 = bias[col], bv1 = bias[col + 1];
            float v00 = acc[mi][ni][0] + bv0, v01 = acc[mi][ni][1] + bv1;
            float v10 = acc[mi][ni][2] + bv0, v11 = acc[mi][ni][3] + bv1;
            if (ROUND) {
                v00 = to_tf32(v00); v01 = to_tf32(v01);
                v10 = to_tf32(v10); v11 = to_tf32(v11);
            }
            if (SPLITOUT == 0) {
                *(float2*)(C + (size_t)r0 * N + col) = make_float2(v00, v01);
                *(float2*)(C + (size_t)(r0 + 8) * N + col) = make_float2(v10, v11);
            } else {
                int part = col / NXC;
                int c = col - part * NXC;
                float* dst = g_qkv + (size_t)part * MROWS * NXC + c;
                *(float2*)(dst + (size_t)r0 * NXC) = make_float2(v00, v01);
                *(float2*)(dst + (size_t)(r0 + 8) * NXC) = make_float2(v10, v11);
            }
        }
    }
}

// ---------------------------------------------------------------------------
// Flash attention, tf32 mma (unchanged core). Epilogue writes g_att in
// A-fragment layout [k8][m16][lane][4] so the proj GEMM reads it directly.
// ---------------------------------------------------------------------------
#define VAST 68
#define KVSTG (64*VAST)

__global__ void __launch_bounds__(256, 2) attn_kernel(const float* __restrict__ amask)
{
    extern __shared__ float kv[];   // [4][64*VAST]: buf0K, buf0V, buf1K, buf1V

    int b  = blockIdx.z;
    int h  = blockIdx.y;
    int qb = 15 - blockIdx.x;       // heavy blocks first (gridDim.x == 16)
    int tid  = threadIdx.x;
    int lane = tid & 31;
    int w    = tid >> 5;
    int lq   = lane >> 2;
    int lr   = lane & 3;
    int r0   = qb * 128;

    const size_t bh = (size_t)b * SEQ * NXC + (size_t)h * SEQ * HD;
    const float* Qg = g_qkv + bh;
    const float* Kg = g_qkv + (size_t)MROWS * NXC + bh;
    const float* Vg = g_qkv + 2ull * MROWS * NXC + bh;
    const float* am = amask + (size_t)b * SEQ;

    // Persistent Q fragments (values already tf32-rounded in g_qkv)
    int qrow = r0 + w * 16 + lq;
    unsigned qa[8][4];
    #pragma unroll
    for (int ks = 0; ks < 8; ks++) {
        qa[ks][0] = F2U(Qg[(size_t)qrow * HD + ks * 8 + lr]);
        qa[ks][1] = F2U(Qg[(size_t)(qrow + 8) * HD + ks * 8 + lr]);
        qa[ks][2] = F2U(Qg[(size_t)qrow * HD + ks * 8 + lr + 4]);
        qa[ks][3] = F2U(Qg[(size_t)(qrow + 8) * HD + ks * 8 + lr + 4]);
    }

    float o[8][4];
    #pragma unroll
    for (int dj = 0; dj < 8; dj++)
        #pragma unroll
        for (int j = 0; j < 4; j++) o[dj][j] = 0.f;
    float m0 = -INFINITY, m1 = -INFINITY, l0 = 0.f, l1 = 0.f;

    const int nkb = 2 * qb + 2;

    auto issue = [&](int kb) {
        float* kd = kv + (kb & 1) * 2 * KVSTG;
        float* vd = kd + KVSTG;
        const float* ks_g = Kg + (size_t)kb * 64 * HD;
        const float* vs_g = Vg + (size_t)kb * 64 * HD;
        #pragma unroll
        for (int i = 0; i < 4; i++) {
            int f = tid + i * 256;          // 0..1023 float4 slots
            int r = f >> 4, cq = (f & 15) << 2;
            cp16(smem_u32(&kd[r * VAST + cq]), ks_g + (size_t)r * HD + cq);
            cp16(smem_u32(&vd[r * VAST + cq]), vs_g + (size_t)r * HD + cq);
        }
        CP_COMMIT();
    };

    issue(0);

    for (int kb = 0; kb < nkb; kb++) {
        if (kb + 1 < nkb) issue(kb + 1);
        CP_WAIT(1);
        __syncthreads();

        const float* Ks = kv + (kb & 1) * 2 * KVSTG;
        const float* Vs = Ks + KVSTG;

        // ---- S = Q @ K^T ----
        float s[8][4];
        #pragma unroll
        for (int ni = 0; ni < 8; ni++)
            #pragma unroll
            for (int j = 0; j < 4; j++) s[ni][j] = 0.f;

        #pragma unroll
        for (int ks = 0; ks < 8; ks++) {
            #pragma unroll
            for (int ni = 0; ni < 8; ni++) {
                int bx = (ni * 8 + lq) * VAST + ks * 8 + lr;
                mma_tf32(s[ni], qa[ks][0], qa[ks][1], qa[ks][2], qa[ks][3],
                         F2U(Ks[bx]), F2U(Ks[bx + 4]));
            }
        }

        // ---- scale + causal mask + attention_mask + row max ----
        bool need_mask = (kb >= 2 * qb);
        float rm0 = -INFINITY, rm1 = -INFINITY;
        #pragma unroll
        for (int ni = 0; ni < 8; ni++) {
            int gc0 = kb * 64 + ni * 8 + 2 * lr;
            float2 amv = *(const float2*)(am + gc0);
            float v00 = s[ni][0] * 0.125f, v01 = s[ni][1] * 0.125f;
            float v10 = s[ni][2] * 0.125f, v11 = s[ni][3] * 0.125f;
            if (need_mask) {
                if (gc0     > qrow)     v00 = -10000.f;
                if (gc0 + 1 > qrow)     v01 = -10000.f;
                if (gc0     > qrow + 8) v10 = -10000.f;
                if (gc0 + 1 > qrow + 8) v11 = -10000.f;
            }
            v00 += amv.x; v01 += amv.y; v10 += amv.x; v11 += amv.y;
            s[ni][0] = v00; s[ni][1] = v01; s[ni][2] = v10; s[ni][3] = v11;
            rm0 = fmaxf(rm0, fmaxf(v00, v01));
            rm1 = fmaxf(rm1, fmaxf(v10, v11));
        }
        #pragma unroll
        for (int off = 1; off <= 2; off <<= 1) {
            rm0 = fmaxf(rm0, __shfl_xor_sync(0xffffffffu, rm0, off));
            rm1 = fmaxf(rm1, __shfl_xor_sync(0xffffffffu, rm1, off));
        }

        // ---- online softmax ----
        float mn0 = fmaxf(m0, rm0), mn1 = fmaxf(m1, rm1);
        float al0 = __expf(m0 - mn0), al1 = __expf(m1 - mn1);
        float rs0 = 0.f, rs1 = 0.f;
        #pragma unroll
        for (int ni = 0; ni < 8; ni++) {
            s[ni][0] = __expf(s[ni][0] - mn0);
            s[ni][1] = __expf(s[ni][1] - mn0);
            s[ni][2] = __expf(s[ni][2] - mn1);
            s[ni][3] = __expf(s[ni][3] - mn1);
            rs0 += s[ni][0] + s[ni][1];
            rs1 += s[ni][2] + s[ni][3];
        }
        #pragma unroll
        for (int off = 1; off <= 2; off <<= 1) {
            rs0 += __shfl_xor_sync(0xffffffffu, rs0, off);
            rs1 += __shfl_xor_sync(0xffffffffu, rs1, off);
        }
        l0 = l0 * al0 + rs0; m0 = mn0;
        l1 = l1 * al1 + rs1; m1 = mn1;
        #pragma unroll
        for (int dj = 0; dj < 8; dj++) {
            o[dj][0] *= al0; o[dj][1] *= al0;
            o[dj][2] *= al1; o[dj][3] *= al1;
        }

        // ---- O += P @ V  (P = S-accum reused as A-frag; V k-index permuted) ----
        #pragma unroll
        for (int ni = 0; ni < 8; ni++) {
            unsigned a0, a1, a2, a3;
            asm("cvt.rna.tf32.f32 %0, %1;" : "=r"(a0) : "f"(s[ni][0]));
            asm("cvt.rna.tf32.f32 %0, %1;" : "=r"(a1) : "f"(s[ni][2]));
            asm("cvt.rna.tf32.f32 %0, %1;" : "=r"(a2) : "f"(s[ni][1]));
            asm("cvt.rna.tf32.f32 %0, %1;" : "=r"(a3) : "f"(s[ni][3]));
            int vrow = (ni * 8 + 2 * lr) * VAST;
            #pragma unroll
            for (int dj = 0; dj < 8; dj++) {
                int bx = vrow + dj * 8 + lq;
                mma_tf32(o[dj], a0, a1, a2, a3,
                         F2U(Vs[bx]), F2U(Vs[bx + VAST]));
            }
        }
        __syncthreads();   // all warps done with this buffer before it refills
    }

    // Epilogue: O / l -> g_att in A-FRAGMENT layout [k8][m16][lane][4].
    // Thread owns rows {qrow, qrow+8}, cols c = h*64 + dj*8 + 2*lr + cc.
    // Frag slot: lane' = lq*4 + (t&3), reg = (t>>2)*2 + rowbit, t = 2*lr+cc.
    float inv0 = 1.0f / l0, inv1 = 1.0f / l1;
    int mg = b * (SEQ / 16) + qb * 8 + w;     // global row / 16
    #pragma unroll
    for (int dj = 0; dj < 8; dj++) {
        int kb2 = h * 8 + dj;                 // global col / 8
        float* basep = g_att + ((size_t)kb2 * (MROWS / 16) + mg) * 128;
        #pragma unroll
        for (int cc = 0; cc < 2; cc++) {
            int t2 = 2 * lr + cc;
            float* p = basep + ((lq * 4 + (t2 & 3)) << 2) + ((t2 >> 2) << 1);
            p[0] = to_tf32(o[dj][cc]     * inv0);   // row qrow
            p[1] = to_tf32(o[dj][2 + cc] * inv1);   // row qrow+8
        }
    }
}

extern "C" void kernel_launch(void* const* d_in, const int* in_sizes, int n_in,
                              void* d_out, int out_size)
{
    const float* x      = (const float*)d_in[0];
    const float* amask  = (const float*)d_in[1];
    const float* w_attn = (const float*)d_in[2];
    const float* b_attn = (const float*)d_in[3];
    const float* w_proj = (const float*)d_in[4];
    const float* b_proj = (const float*)d_in[5];
    float* out = (float*)d_out;

    // Device addresses of __device__ symbols (host-side symbol use is invalid;
    // with ATS it silently reads host memory — round-4 lesson).
    float *gx, *gwa, *gwp, *gatt;
    cudaGetSymbolAddress((void**)&gx,   g_x);
    cudaGetSymbolAddress((void**)&gwa,  g_wa);
    cudaGetSymbolAddress((void**)&gwp,  g_wp);
    cudaGetSymbolAddress((void**)&gatt, g_att);

    // 0) pack+round inputs into fragment layouts
    packA_kernel<<<(96 * 256 * 32) / 256, 256>>>(x, gx, MROWS, NXC);
    packB_kernel<<<(96 * 288 * 32) / 256, 256>>>(w_attn, gwa, NXC, QKVN);
    packB_kernel<<<(96 * 96 * 32) / 256, 256>>>(w_proj, gwp, NXC, NXC);

    const int gsmem = 6 * GSTG * 4;   // 49,152 B
    cudaFuncSetAttribute(gemm_tc<1, 1>,
                         cudaFuncAttributeMaxDynamicSharedMemorySize, gsmem);
    cudaFuncSetAttribute(gemm_tc<0, 0>,
                         cudaFuncAttributeMaxDynamicSharedMemorySize, gsmem);
    cudaFuncSetAttribute(attn_kernel,
                         cudaFuncAttributeMaxDynamicSharedMemorySize, 4 * KVSTG * 4);

    // 1) QKV projection -> g_qkv (tf32-rounded split, row-major)
    gemm_tc<1, 1><<<dim3(QKVN / 128, MROWS / 128), 256, gsmem>>>(
        gx, gwa, b_attn, nullptr, MROWS, QKVN, NXC);

    // 2) Flash attention (69.6 KB dynamic smem); writes g_att frag-packed
    attn_kernel<<<dim3(SEQ / 128, NH, BSZ), 256, 4 * KVSTG * 4>>>(amask);

    // 3) Output projection -> d_out (exact fp32 out)
    gemm_tc<0, 0><<<dim3(NXC / 128, MROWS / 128), 256, gsmem>>>(
        gatt, gwp, b_proj, out, MROWS, NXC, NXC);
}

// round 9
// speedup vs baseline: 4.5213x; 1.1406x over previous
#include <cuda_runtime.h>
#include <cuda_fp16.h>
#include <math.h>

#define SEQ   2048
#define NXC   768
#define NH    12
#define HD    64
#define BSZ   2
#define MROWS (BSZ*SEQ)      // 4096
#define QKVN  (3*NXC)        // 2304

// Scratch (static __device__ — no allocations allowed). All fp16.
// g_qkv: [3][MROWS][NXC] row-major halves (Q part pre-scaled by 0.125).
// g_att: proj-A fragment-packed [k16][m16][lane][4xhalf2]
// g_x:   A-frag packed;  g_wa/g_wp: B-frag packed [k16][n8][lane][2xhalf2]
__device__ __align__(16) __half g_qkv[3ull * MROWS * NXC];
__device__ __align__(16) __half g_att[(size_t)MROWS * NXC];
__device__ __align__(16) __half g_x [(size_t)MROWS * NXC];
__device__ __align__(16) __half g_wa[(size_t)NXC * QKVN];
__device__ __align__(16) __half g_wp[(size_t)NXC * NXC];

__device__ __forceinline__ unsigned h2u(float lo, float hi) {
    __half2 h = __floats2half2_rn(lo, hi);
    return *reinterpret_cast<unsigned*>(&h);
}

__device__ __forceinline__ void mma_f16(float* d,
    unsigned a0, unsigned a1, unsigned a2, unsigned a3,
    unsigned b0, unsigned b1)
{
    asm volatile(
        "mma.sync.aligned.m16n8k16.row.col.f32.f16.f16.f32 "
        "{%0,%1,%2,%3},{%4,%5,%6,%7},{%8,%9},{%0,%1,%2,%3};"
        : "+f"(d[0]), "+f"(d[1]), "+f"(d[2]), "+f"(d[3])
        : "r"(a0), "r"(a1), "r"(a2), "r"(a3), "r"(b0), "r"(b1));
}

__device__ __forceinline__ void ldmx2t(unsigned& r0, unsigned& r1, unsigned addr) {
    asm volatile("ldmatrix.sync.aligned.m8n8.x2.trans.shared.b16 {%0,%1}, [%2];"
                 : "=r"(r0), "=r"(r1) : "r"(addr));
}

__device__ __forceinline__ void cp16(unsigned dst, const void* src) {
    asm volatile("cp.async.cg.shared.global [%0], [%1], 16;"
                 :: "r"(dst), "l"(src));
}
#define CP_COMMIT()  asm volatile("cp.async.commit_group;")
#define CP_WAIT(n)   asm volatile("cp.async.wait_group " #n ";")
__device__ __forceinline__ unsigned smem_u32(const void* p) {
    return (unsigned)__cvta_generic_to_shared(p);
}

// ---------------------------------------------------------------------------
// Pack kernels: fp16-round AND permute into m16n8k16 fragment order.
// A-frag: a0={r,2lr..+1} a1={r+8,..} a2={r,2lr+8..+9} a3={r+8,..}  (4 half2)
// B-frag: b0={B[2lr][lq],B[2lr+1][lq]} b1={B[2lr+8][lq],B[2lr+9][lq]} (2 half2)
// ---------------------------------------------------------------------------
__global__ void packA_kernel(const float* __restrict__ src, __half* __restrict__ dst,
                             int M, int K)
{
    int idx = blockIdx.x * blockDim.x + threadIdx.x;   // one per [k16][mg][lane]
    int lane = idx & 31;
    int mg   = (idx >> 5) & ((M / 16) - 1);            // M/16 = 256 (pow2)
    int kb   = idx / (32 * (M / 16));
    if (kb >= K / 16) return;
    int lq = lane >> 2, lr = lane & 3;
    const float* s = src + (size_t)(mg * 16 + lq) * K + kb * 16 + 2 * lr;
    uint4 v;
    v.x = h2u(s[0],         s[1]);
    v.y = h2u(s[8 * K],     s[8 * K + 1]);
    v.z = h2u(s[8],         s[9]);
    v.w = h2u(s[8 * K + 8], s[8 * K + 9]);
    *(uint4*)(dst + (size_t)idx * 8) = v;
}

__global__ void packB_kernel(const float* __restrict__ src, __half* __restrict__ dst,
                             int K, int N)
{
    int idx = blockIdx.x * blockDim.x + threadIdx.x;   // one per [k16][ng][lane]
    int lane = idx & 31;
    int ng   = (idx >> 5) % (N / 8);
    int kb   = idx / (32 * (N / 8));
    if (kb >= K / 16) return;
    int lq = lane >> 2, lr = lane & 3;
    const float* s = src + (size_t)(kb * 16 + 2 * lr) * N + ng * 8 + lq;
    uint2 v;
    v.x = h2u(s[0],     s[N]);
    v.y = h2u(s[8 * N], s[9 * N]);
    *(uint2*)(dst + (size_t)idx * 4) = v;
}

// ---------------------------------------------------------------------------
// fp16 GEMM on fragment-packed operands. C[M,N] = A@B + bias.
// Block 128x128, BK=32 (two k16 slabs/stage), 3-stage cp.async, 8 warps
// (2m x 4n), warp tile 64x32. Per k16: 4 LDS.128 + 4 LDS.64 + 16 mma.
// SPLITOUT=1: half2 scatter into g_qkv (Q part pre-scaled by 0.125).
// SPLITOUT=0: fp32 output + bias (exact).
// ---------------------------------------------------------------------------
template<int SPLITOUT>
__global__ void __launch_bounds__(256, 2)
gemm_tc(const __half* __restrict__ A, const __half* __restrict__ B,
        const float* __restrict__ bias, float* __restrict__ C,
        int M, int N, int K)
{
    __shared__ __half sg[24576];    // As[3][4096] + Bs[3][4096] halves = 48KB
    __half* As = sg;
    __half* Bs = sg + 12288;

    int tid  = threadIdx.x;
    int lane = tid & 31;
    int w    = tid >> 5;
    int wm   = w & 1;
    int wn   = w >> 1;
    int lq   = lane >> 2;
    int lr   = lane & 3;

    int brow16 = blockIdx.y * 8;
    int bcol8  = blockIdx.x * 16;
    const int M16 = M / 16, N8 = N / 8;

    float acc[4][4][4];
    #pragma unroll
    for (int mi = 0; mi < 4; mi++)
        #pragma unroll
        for (int ni = 0; ni < 4; ni++)
            #pragma unroll
            for (int j = 0; j < 4; j++) acc[mi][ni][j] = 0.f;

    const int NT = K / 32;

    auto issue = [&](int t, int s) {
        __half* as = As + s * 4096;
        __half* bs = Bs + s * 4096;
        const __half* gA = A + ((size_t)(2 * t) * M16 + brow16) * 256 + tid * 8;
        cp16(smem_u32(as + tid * 8),        gA);
        cp16(smem_u32(as + 2048 + tid * 8), gA + (size_t)M16 * 256);
        const __half* gB = B + ((size_t)(2 * t) * N8 + bcol8) * 128 + tid * 8;
        cp16(smem_u32(bs + tid * 8),        gB);
        cp16(smem_u32(bs + 2048 + tid * 8), gB + (size_t)N8 * 128);
        CP_COMMIT();
    };

    issue(0, 0);
    issue(1, 1);

    for (int t = 0; t < NT; t++) {
        CP_WAIT(1);
        __syncthreads();
        if (t + 2 < NT) issue(t + 2, (t + 2) % 3);

        const __half* as0 = As + (t % 3) * 4096 + wm * 1024 + lane * 8;
        const __half* bs0 = Bs + (t % 3) * 4096 + wn * 512 + lane * 4;
        #pragma unroll
        for (int kk = 0; kk < 2; kk++) {
            const __half* as = as0 + kk * 2048;
            const __half* bs = bs0 + kk * 2048;
            uint4 af[4];
            #pragma unroll
            for (int mi = 0; mi < 4; mi++)
                af[mi] = *(const uint4*)(as + mi * 256);
            #pragma unroll
            for (int ni = 0; ni < 4; ni++) {
                uint2 bf = *(const uint2*)(bs + ni * 128);
                #pragma unroll
                for (int mi = 0; mi < 4; mi++)
                    mma_f16(acc[mi][ni], af[mi].x, af[mi].y, af[mi].z, af[mi].w,
                            bf.x, bf.y);
            }
        }
    }

    // Epilogue
    #pragma unroll
    for (int mi = 0; mi < 4; mi++) {
        int r0 = brow16 * 16 + wm * 64 + mi * 16 + lq;
        #pragma unroll
        for (int ni = 0; ni < 4; ni++) {
            int col = bcol8 * 8 + wn * 32 + ni * 8 + lr * 2;
            float bv0 = bias[col], bv1 = bias[col + 1];
            float v00 = acc[mi][ni][0] + bv0, v01 = acc[mi][ni][1] + bv1;
            float v10 = acc[mi][ni][2] + bv0, v11 = acc[mi][ni][3] + bv1;
            if (SPLITOUT == 0) {
                *(float2*)(C + (size_t)r0 * N + col) = make_float2(v00, v01);
                *(float2*)(C + (size_t)(r0 + 8) * N + col) = make_float2(v10, v11);
            } else {
                int part = col / NXC;
                int c = col - part * NXC;
                float sc = (part == 0) ? 0.125f : 1.0f;   // exact pow2: bit-neutral
                __half* dst = g_qkv + (size_t)part * MROWS * NXC + c;
                *(unsigned*)(dst + (size_t)r0 * NXC) = h2u(v00 * sc, v01 * sc);
                *(unsigned*)(dst + (size_t)(r0 + 8) * NXC) = h2u(v10 * sc, v11 * sc);
            }
        }
    }
}

// ---------------------------------------------------------------------------
// Flash attention, fp16 m16n8k16. Block = 128 q-rows, tiles of 64 keys,
// 8 warps x 16 q-rows. Q frags persistent in regs (pre-scaled by 0.125).
// K/V double-buffered cp.async with XOR-16B swizzle; V via ldmatrix.x2.trans;
// P packed to half2 directly from S accumulators. smem = 32 KB static.
// ---------------------------------------------------------------------------
__global__ void __launch_bounds__(256, 2) attn_kernel(const float* __restrict__ amask)
{
    __shared__ __half kvs[2][2][4096];   // [stage][K/V][64 rows x 64 halves]

    int b  = blockIdx.z;
    int h  = blockIdx.y;
    int qb = 15 - blockIdx.x;       // heavy blocks first
    int tid  = threadIdx.x;
    int lane = tid & 31;
    int w    = tid >> 5;
    int lq   = lane >> 2;
    int lr   = lane & 3;

    const size_t bh = (size_t)b * SEQ * NXC + (size_t)h * SEQ * HD;
    const __half* Qg = g_qkv + bh;
    const __half* Kg = g_qkv + (size_t)MROWS * NXC + bh;
    const __half* Vg = g_qkv + 2ull * MROWS * NXC + bh;
    const float* am = amask + (size_t)b * SEQ;

    // Persistent Q fragments (already fp16, already x0.125)
    int qrow = qb * 128 + w * 16 + lq;
    const __half* qr  = Qg + (size_t)qrow * HD;
    const __half* qr8 = Qg + (size_t)(qrow + 8) * HD;
    unsigned qa[4][4];
    #pragma unroll
    for (int ks = 0; ks < 4; ks++) {
        qa[ks][0] = *(const unsigned*)(qr  + ks * 16 + 2 * lr);
        qa[ks][1] = *(const unsigned*)(qr8 + ks * 16 + 2 * lr);
        qa[ks][2] = *(const unsigned*)(qr  + ks * 16 + 2 * lr + 8);
        qa[ks][3] = *(const unsigned*)(qr8 + ks * 16 + 2 * lr + 8);
    }

    float o[8][4];
    #pragma unroll
    for (int dj = 0; dj < 8; dj++)
        #pragma unroll
        for (int j = 0; j < 4; j++) o[dj][j] = 0.f;
    float m0 = -INFINITY, m1 = -INFINITY, l0 = 0.f, l1 = 0.f;

    const int nkb = 2 * qb + 2;

    // XOR-16B swizzle: row r, 16B-chunk c -> chunk c^(r&7). cp16 = one chunk.
    auto issue = [&](int kb) {
        __half* kd = kvs[kb & 1][0];
        __half* vd = kvs[kb & 1][1];
        const __half* kg = Kg + (size_t)kb * 64 * HD;
        const __half* vg = Vg + (size_t)kb * 64 * HD;
        #pragma unroll
        for (int i = 0; i < 2; i++) {
            int f = tid + i * 256;          // 0..511 chunks
            int r = f >> 3, c = f & 7;
            int sw = r * 64 + ((c ^ (r & 7)) << 3);
            cp16(smem_u32(kd + sw), kg + r * 64 + c * 8);
            cp16(smem_u32(vd + sw), vg + r * 64 + c * 8);
        }
        CP_COMMIT();
    };

    issue(0);

    for (int kb = 0; kb < nkb; kb++) {
        if (kb + 1 < nkb) issue(kb + 1);
        CP_WAIT(1);
        __syncthreads();

        const __half* Ks = kvs[kb & 1][0];
        const __half* Vs = kvs[kb & 1][1];

        // ---- S = (Q*0.125) @ K^T ----
        float s[8][4];
        #pragma unroll
        for (int ni = 0; ni < 8; ni++)
            #pragma unroll
            for (int j = 0; j < 4; j++) s[ni][j] = 0.f;

        #pragma unroll
        for (int ks = 0; ks < 4; ks++) {
            #pragma unroll
            for (int ni = 0; ni < 8; ni++) {
                int key = ni * 8 + lq;
                const __half* base = Ks + key * 64 + 2 * lr;
                unsigned b0 = *(const unsigned*)(base + (((2*ks  ) ^ (key & 7)) << 3));
                unsigned b1 = *(const unsigned*)(base + (((2*ks+1) ^ (key & 7)) << 3));
                mma_f16(s[ni], qa[ks][0], qa[ks][1], qa[ks][2], qa[ks][3], b0, b1);
            }
        }

        // ---- causal mask + attention_mask + row max ----
        bool need_mask = (kb >= 2 * qb);
        float rm0 = -INFINITY, rm1 = -INFINITY;
        #pragma unroll
        for (int ni = 0; ni < 8; ni++) {
            int gc0 = kb * 64 + ni * 8 + 2 * lr;
            float2 amv = *(const float2*)(am + gc0);
            float v00 = s[ni][0], v01 = s[ni][1];
            float v10 = s[ni][2], v11 = s[ni][3];
            if (need_mask) {
                if (gc0     > qrow)     v00 = -10000.f;
                if (gc0 + 1 > qrow)     v01 = -10000.f;
                if (gc0     > qrow + 8) v10 = -10000.f;
                if (gc0 + 1 > qrow + 8) v11 = -10000.f;
            }
            v00 += amv.x; v01 += amv.y; v10 += amv.x; v11 += amv.y;
            s[ni][0] = v00; s[ni][1] = v01; s[ni][2] = v10; s[ni][3] = v11;
            rm0 = fmaxf(rm0, fmaxf(v00, v01));
            rm1 = fmaxf(rm1, fmaxf(v10, v11));
        }
        #pragma unroll
        for (int off = 1; off <= 2; off <<= 1) {
            rm0 = fmaxf(rm0, __shfl_xor_sync(0xffffffffu, rm0, off));
            rm1 = fmaxf(rm1, __shfl_xor_sync(0xffffffffu, rm1, off));
        }

        // ---- online softmax ----
        float mn0 = fmaxf(m0, rm0), mn1 = fmaxf(m1, rm1);
        float al0 = __expf(m0 - mn0), al1 = __expf(m1 - mn1);
        float rs0 = 0.f, rs1 = 0.f;
        #pragma unroll
        for (int ni = 0; ni < 8; ni++) {
            s[ni][0] = __expf(s[ni][0] - mn0);
            s[ni][1] = __expf(s[ni][1] - mn0);
            s[ni][2] = __expf(s[ni][2] - mn1);
            s[ni][3] = __expf(s[ni][3] - mn1);
            rs0 += s[ni][0] + s[ni][1];
            rs1 += s[ni][2] + s[ni][3];
        }
        #pragma unroll
        for (int off = 1; off <= 2; off <<= 1) {
            rs0 += __shfl_xor_sync(0xffffffffu, rs0, off);
            rs1 += __shfl_xor_sync(0xffffffffu, rs1, off);
        }
        l0 = l0 * al0 + rs0; m0 = mn0;
        l1 = l1 * al1 + rs1; m1 = mn1;
        #pragma unroll
        for (int dj = 0; dj < 8; dj++) {
            o[dj][0] *= al0; o[dj][1] *= al0;
            o[dj][2] *= al1; o[dj][3] *= al1;
        }

        // ---- O += P @ V  (P half2-packed from S accums; V via ldmatrix.trans) ----
        #pragma unroll
        for (int t = 0; t < 4; t++) {    // k16 block over keys 16t..16t+15
            unsigned a0 = h2u(s[2*t][0],   s[2*t][1]);
            unsigned a1 = h2u(s[2*t][2],   s[2*t][3]);
            unsigned a2 = h2u(s[2*t+1][0], s[2*t+1][1]);
            unsigned a3 = h2u(s[2*t+1][2], s[2*t+1][3]);
            int row = 16 * t + (lane & 15);
            #pragma unroll
            for (int dj = 0; dj < 8; dj++) {
                unsigned addr = smem_u32(Vs + row * 64 + ((dj ^ (row & 7)) << 3));
                unsigned b0, b1;
                ldmx2t(b0, b1, addr);
                mma_f16(o[dj], a0, a1, a2, a3, b0, b1);
            }
        }
        __syncthreads();   // all warps done with buffer before it refills
    }

    // Epilogue: O / l -> g_att in fp16 A-frag layout [k16][m16][lane][4xhalf2].
    // Thread's col pair (dj*8+2lr, +1) IS one frag half2 owned by this lane:
    // k16 = h*4 + dj/2, reg = (dj&1)*2 + rowbit.
    float inv0 = 1.0f / l0, inv1 = 1.0f / l1;
    int mg = b * (SEQ / 16) + qb * 8 + w;
    #pragma unroll
    for (int dj = 0; dj < 8; dj++) {
        int kg16 = h * 4 + (dj >> 1);
        __half* p = g_att + ((size_t)(kg16 * (MROWS / 16) + mg) * 32 + lane) * 8
                          + (dj & 1) * 4;
        *(unsigned*)(p)     = h2u(o[dj][0] * inv0, o[dj][1] * inv0);  // reg a0/a2
        *(unsigned*)(p + 2) = h2u(o[dj][2] * inv1, o[dj][3] * inv1);  // reg a1/a3
    }
}

extern "C" void kernel_launch(void* const* d_in, const int* in_sizes, int n_in,
                              void* d_out, int out_size)
{
    const float* x      = (const float*)d_in[0];
    const float* amask  = (const float*)d_in[1];
    const float* w_attn = (const float*)d_in[2];
    const float* b_attn = (const float*)d_in[3];
    const float* w_proj = (const float*)d_in[4];
    const float* b_proj = (const float*)d_in[5];
    float* out = (float*)d_out;

    // Device addresses of __device__ symbols (round-4 lesson: never pass the
    // host shadow of a __device__ symbol as a kernel arg).
    __half *gx, *gwa, *gwp, *gatt;
    cudaGetSymbolAddress((void**)&gx,   g_x);
    cudaGetSymbolAddress((void**)&gwa,  g_wa);
    cudaGetSymbolAddress((void**)&gwp,  g_wp);
    cudaGetSymbolAddress((void**)&gatt, g_att);

    // 0) pack inputs into fp16 fragment layouts
    packA_kernel<<<(48 * 256 * 32) / 256, 256>>>(x, gx, MROWS, NXC);
    packB_kernel<<<(48 * 288 * 32) / 256, 256>>>(w_attn, gwa, NXC, QKVN);
    packB_kernel<<<(48 * 96 * 32) / 256, 256>>>(w_proj, gwp, NXC, NXC);

    // 1) QKV projection -> g_qkv halves (Q pre-scaled by 0.125)
    gemm_tc<1><<<dim3(QKVN / 128, MROWS / 128), 256>>>(
        gx, gwa, b_attn, nullptr, MROWS, QKVN, NXC);

    // 2) Flash attention (32 KB static smem); writes g_att frag-packed fp16
    attn_kernel<<<dim3(SEQ / 128, NH, BSZ), 256>>>(amask);

    // 3) Output projection -> d_out (fp32)
    gemm_tc<0><<<dim3(NXC / 128, MROWS / 128), 256>>>(
        gatt, gwp, b_proj, out, MROWS, NXC, NXC);
}

// round 10
// speedup vs baseline: 7.4186x; 1.6408x over previous
#include <cuda_runtime.h>
#include <cuda_fp16.h>
#include <math.h>

#define SEQ   2048
#define NXC   768
#define NH    12
#define HD    64
#define BSZ   2
#define MROWS (BSZ*SEQ)      // 4096
#define QKVN  (3*NXC)        // 2304

#define LOG2E  1.4426950408889634f
#define MASKEDL (-10000.0f * LOG2E)

// Scratch (static __device__ — no allocations allowed). All fp16.
// g_qkv: [3][MROWS][NXC] row-major halves (Q part pre-scaled by 0.125*log2e).
// g_att: proj-A fragment-packed [k16][m16][lane][4xhalf2]
// g_x:   A-frag packed;  g_wa/g_wp: B-frag packed [k16][n8][lane][2xhalf2]
__device__ __align__(16) __half g_qkv[3ull * MROWS * NXC];
__device__ __align__(16) __half g_att[(size_t)MROWS * NXC];
__device__ __align__(16) __half g_x [(size_t)MROWS * NXC];
__device__ __align__(16) __half g_wa[(size_t)NXC * QKVN];
__device__ __align__(16) __half g_wp[(size_t)NXC * NXC];

__device__ __forceinline__ unsigned h2u(float lo, float hi) {
    __half2 h = __floats2half2_rn(lo, hi);
    return *reinterpret_cast<unsigned*>(&h);
}

__device__ __forceinline__ void mma_f16(float* d,
    unsigned a0, unsigned a1, unsigned a2, unsigned a3,
    unsigned b0, unsigned b1)
{
    asm volatile(
        "mma.sync.aligned.m16n8k16.row.col.f32.f16.f16.f32 "
        "{%0,%1,%2,%3},{%4,%5,%6,%7},{%8,%9},{%0,%1,%2,%3};"
        : "+f"(d[0]), "+f"(d[1]), "+f"(d[2]), "+f"(d[3])
        : "r"(a0), "r"(a1), "r"(a2), "r"(a3), "r"(b0), "r"(b1));
}

__device__ __forceinline__ void ldmx2t(unsigned& r0, unsigned& r1, unsigned addr) {
    asm volatile("ldmatrix.sync.aligned.m8n8.x2.trans.shared.b16 {%0,%1}, [%2];"
                 : "=r"(r0), "=r"(r1) : "r"(addr));
}

__device__ __forceinline__ unsigned ex2_h2(unsigned x) {
    unsigned r;
    asm("ex2.approx.f16x2 %0, %1;" : "=r"(r) : "r"(x));
    return r;
}
__device__ __forceinline__ float ex2_f(float x) {
    float r;
    asm("ex2.approx.f32 %0, %1;" : "=f"(r) : "f"(x));
    return r;
}

__device__ __forceinline__ void cp16(unsigned dst, const void* src) {
    asm volatile("cp.async.cg.shared.global [%0], [%1], 16;"
                 :: "r"(dst), "l"(src));
}
#define CP_COMMIT()  asm volatile("cp.async.commit_group;")
#define CP_WAIT(n)   asm volatile("cp.async.wait_group " #n ";")
__device__ __forceinline__ unsigned smem_u32(const void* p) {
    return (unsigned)__cvta_generic_to_shared(p);
}

// ---------------------------------------------------------------------------
// Pack kernels: fp16-round AND permute into m16n8k16 fragment order.
// ---------------------------------------------------------------------------
__global__ void packA_kernel(const float* __restrict__ src, __half* __restrict__ dst,
                             int M, int K)
{
    int idx = blockIdx.x * blockDim.x + threadIdx.x;   // one per [k16][mg][lane]
    int lane = idx & 31;
    int mg   = (idx >> 5) & ((M / 16) - 1);            // M/16 = 256 (pow2)
    int kb   = idx / (32 * (M / 16));
    if (kb >= K / 16) return;
    int lq = lane >> 2, lr = lane & 3;
    const float* s = src + (size_t)(mg * 16 + lq) * K + kb * 16 + 2 * lr;
    uint4 v;
    v.x = h2u(s[0],         s[1]);
    v.y = h2u(s[8 * K],     s[8 * K + 1]);
    v.z = h2u(s[8],         s[9]);
    v.w = h2u(s[8 * K + 8], s[8 * K + 9]);
    *(uint4*)(dst + (size_t)idx * 8) = v;
}

__global__ void packB_kernel(const float* __restrict__ src, __half* __restrict__ dst,
                             int K, int N)
{
    int idx = blockIdx.x * blockDim.x + threadIdx.x;   // one per [k16][ng][lane]
    int lane = idx & 31;
    int ng   = (idx >> 5) % (N / 8);
    int kb   = idx / (32 * (N / 8));
    if (kb >= K / 16) return;
    int lq = lane >> 2, lr = lane & 3;
    const float* s = src + (size_t)(kb * 16 + 2 * lr) * N + ng * 8 + lq;
    uint2 v;
    v.x = h2u(s[0],     s[N]);
    v.y = h2u(s[8 * N], s[9 * N]);
    *(uint2*)(dst + (size_t)idx * 4) = v;
}

// ---------------------------------------------------------------------------
// fp16 GEMM on fragment-packed operands (frozen from round 9, except the Q
// pre-scale constant now includes log2e).
// ---------------------------------------------------------------------------
template<int SPLITOUT>
__global__ void __launch_bounds__(256, 2)
gemm_tc(const __half* __restrict__ A, const __half* __restrict__ B,
        const float* __restrict__ bias, float* __restrict__ C,
        int M, int N, int K)
{
    __shared__ __half sg[24576];    // As[3][4096] + Bs[3][4096] halves = 48KB
    __half* As = sg;
    __half* Bs = sg + 12288;

    int tid  = threadIdx.x;
    int lane = tid & 31;
    int w    = tid >> 5;
    int wm   = w & 1;
    int wn   = w >> 1;
    int lq   = lane >> 2;
    int lr   = lane & 3;

    int brow16 = blockIdx.y * 8;
    int bcol8  = blockIdx.x * 16;
    const int M16 = M / 16, N8 = N / 8;

    float acc[4][4][4];
    #pragma unroll
    for (int mi = 0; mi < 4; mi++)
        #pragma unroll
        for (int ni = 0; ni < 4; ni++)
            #pragma unroll
            for (int j = 0; j < 4; j++) acc[mi][ni][j] = 0.f;

    const int NT = K / 32;

    auto issue = [&](int t, int s) {
        __half* as = As + s * 4096;
        __half* bs = Bs + s * 4096;
        const __half* gA = A + ((size_t)(2 * t) * M16 + brow16) * 256 + tid * 8;
        cp16(smem_u32(as + tid * 8),        gA);
        cp16(smem_u32(as + 2048 + tid * 8), gA + (size_t)M16 * 256);
        const __half* gB = B + ((size_t)(2 * t) * N8 + bcol8) * 128 + tid * 8;
        cp16(smem_u32(bs + tid * 8),        gB);
        cp16(smem_u32(bs + 2048 + tid * 8), gB + (size_t)N8 * 128);
        CP_COMMIT();
    };

    issue(0, 0);
    issue(1, 1);

    for (int t = 0; t < NT; t++) {
        CP_WAIT(1);
        __syncthreads();
        if (t + 2 < NT) issue(t + 2, (t + 2) % 3);

        const __half* as0 = As + (t % 3) * 4096 + wm * 1024 + lane * 8;
        const __half* bs0 = Bs + (t % 3) * 4096 + wn * 512 + lane * 4;
        #pragma unroll
        for (int kk = 0; kk < 2; kk++) {
            const __half* as = as0 + kk * 2048;
            const __half* bs = bs0 + kk * 2048;
            uint4 af[4];
            #pragma unroll
            for (int mi = 0; mi < 4; mi++)
                af[mi] = *(const uint4*)(as + mi * 256);
            #pragma unroll
            for (int ni = 0; ni < 4; ni++) {
                uint2 bf = *(const uint2*)(bs + ni * 128);
                #pragma unroll
                for (int mi = 0; mi < 4; mi++)
                    mma_f16(acc[mi][ni], af[mi].x, af[mi].y, af[mi].z, af[mi].w,
                            bf.x, bf.y);
            }
        }
    }

    // Epilogue
    #pragma unroll
    for (int mi = 0; mi < 4; mi++) {
        int r0 = brow16 * 16 + wm * 64 + mi * 16 + lq;
        #pragma unroll
        for (int ni = 0; ni < 4; ni++) {
            int col = bcol8 * 8 + wn * 32 + ni * 8 + lr * 2;
            float bv0 = bias[col], bv1 = bias[col + 1];
            float v00 = acc[mi][ni][0] + bv0, v01 = acc[mi][ni][1] + bv1;
            float v10 = acc[mi][ni][2] + bv0, v11 = acc[mi][ni][3] + bv1;
            if (SPLITOUT == 0) {
                *(float2*)(C + (size_t)r0 * N + col) = make_float2(v00, v01);
                *(float2*)(C + (size_t)(r0 + 8) * N + col) = make_float2(v10, v11);
            } else {
                int part = col / NXC;
                int c = col - part * NXC;
                // Q pre-scaled by 0.125*log2e: softmax runs in exp2 domain.
                float sc = (part == 0) ? (0.125f * LOG2E) : 1.0f;
                __half* dst = g_qkv + (size_t)part * MROWS * NXC + c;
                *(unsigned*)(dst + (size_t)r0 * NXC) = h2u(v00 * sc, v01 * sc);
                *(unsigned*)(dst + (size_t)(r0 + 8) * NXC) = h2u(v10 * sc, v11 * sc);
            }
        }
    }
}

// ---------------------------------------------------------------------------
// Flash attention, fp16 m16n8k16, exp2-domain softmax.
// S is computed in log2 units (Q pre-scaled). P = ex2.approx.f16x2 of packed
// (s-m) pairs -> results ARE the PV A-fragments. Row sums l via ones-mma.
// ---------------------------------------------------------------------------
__global__ void __launch_bounds__(256, 2) attn_kernel(const float* __restrict__ amask)
{
    __shared__ __half kvs[2][2][4096];   // [stage][K/V][64 rows x 64 halves]

    int b  = blockIdx.z;
    int h  = blockIdx.y;
    int qb = 15 - blockIdx.x;       // heavy blocks first
    int tid  = threadIdx.x;
    int lane = tid & 31;
    int w    = tid >> 5;
    int lq   = lane >> 2;
    int lr   = lane & 3;

    const size_t bh = (size_t)b * SEQ * NXC + (size_t)h * SEQ * HD;
    const __half* Qg = g_qkv + bh;
    const __half* Kg = g_qkv + (size_t)MROWS * NXC + bh;
    const __half* Vg = g_qkv + 2ull * MROWS * NXC + bh;
    const float* am = amask + (size_t)b * SEQ;

    // Persistent Q fragments (already fp16, already x 0.125*log2e)
    int qrow = qb * 128 + w * 16 + lq;
    const __half* qr  = Qg + (size_t)qrow * HD;
    const __half* qr8 = Qg + (size_t)(qrow + 8) * HD;
    unsigned qa[4][4];
    #pragma unroll
    for (int ks = 0; ks < 4; ks++) {
        qa[ks][0] = *(const unsigned*)(qr  + ks * 16 + 2 * lr);
        qa[ks][1] = *(const unsigned*)(qr8 + ks * 16 + 2 * lr);
        qa[ks][2] = *(const unsigned*)(qr  + ks * 16 + 2 * lr + 8);
        qa[ks][3] = *(const unsigned*)(qr8 + ks * 16 + 2 * lr + 8);
    }

    float o[8][4];
    #pragma unroll
    for (int dj = 0; dj < 8; dj++)
        #pragma unroll
        for (int j = 0; j < 4; j++) o[dj][j] = 0.f;
    float m0 = -INFINITY, m1 = -INFINITY, l0 = 0.f, l1 = 0.f;

    const int nkb = 2 * qb + 2;

    // XOR-16B swizzle: row r, 16B-chunk c -> chunk c^(r&7). cp16 = one chunk.
    auto issue = [&](int kb) {
        __half* kd = kvs[kb & 1][0];
        __half* vd = kvs[kb & 1][1];
        const __half* kg = Kg + (size_t)kb * 64 * HD;
        const __half* vg = Vg + (size_t)kb * 64 * HD;
        #pragma unroll
        for (int i = 0; i < 2; i++) {
            int f = tid + i * 256;          // 0..511 chunks
            int r = f >> 3, c = f & 7;
            int sw = r * 64 + ((c ^ (r & 7)) << 3);
            cp16(smem_u32(kd + sw), kg + r * 64 + c * 8);
            cp16(smem_u32(vd + sw), vg + r * 64 + c * 8);
        }
        CP_COMMIT();
    };

    issue(0);

    for (int kb = 0; kb < nkb; kb++) {
        if (kb + 1 < nkb) issue(kb + 1);
        CP_WAIT(1);
        __syncthreads();

        const __half* Ks = kvs[kb & 1][0];
        const __half* Vs = kvs[kb & 1][1];

        // ---- S = (Q * 0.125 * log2e) @ K^T  (log2-domain scores) ----
        float s[8][4];
        #pragma unroll
        for (int ni = 0; ni < 8; ni++)
            #pragma unroll
            for (int j = 0; j < 4; j++) s[ni][j] = 0.f;

        #pragma unroll
        for (int ks = 0; ks < 4; ks++) {
            #pragma unroll
            for (int ni = 0; ni < 8; ni++) {
                int key = ni * 8 + lq;
                const __half* base = Ks + key * 64 + 2 * lr;
                unsigned b0 = *(const unsigned*)(base + (((2*ks  ) ^ (key & 7)) << 3));
                unsigned b1 = *(const unsigned*)(base + (((2*ks+1) ^ (key & 7)) << 3));
                mma_f16(s[ni], qa[ks][0], qa[ks][1], qa[ks][2], qa[ks][3], b0, b1);
            }
        }

        // ---- causal mask + attention_mask*log2e (FMA) + row max ----
        bool need_mask = (kb >= 2 * qb);
        float rm0 = -INFINITY, rm1 = -INFINITY;
        #pragma unroll
        for (int ni = 0; ni < 8; ni++) {
            int gc0 = kb * 64 + ni * 8 + 2 * lr;
            float2 amv = *(const float2*)(am + gc0);
            float b00 = s[ni][0], b01 = s[ni][1];
            float b10 = s[ni][2], b11 = s[ni][3];
            if (need_mask) {
                if (gc0     > qrow)     b00 = MASKEDL;
                if (gc0 + 1 > qrow)     b01 = MASKEDL;
                if (gc0     > qrow + 8) b10 = MASKEDL;
                if (gc0 + 1 > qrow + 8) b11 = MASKEDL;
            }
            float v00 = fmaf(amv.x, LOG2E, b00);
            float v01 = fmaf(amv.y, LOG2E, b01);
            float v10 = fmaf(amv.x, LOG2E, b10);
            float v11 = fmaf(amv.y, LOG2E, b11);
            s[ni][0] = v00; s[ni][1] = v01; s[ni][2] = v10; s[ni][3] = v11;
            rm0 = fmaxf(rm0, fmaxf(v00, v01));
            rm1 = fmaxf(rm1, fmaxf(v10, v11));
        }
        #pragma unroll
        for (int off = 1; off <= 2; off <<= 1) {
            rm0 = fmaxf(rm0, __shfl_xor_sync(0xffffffffu, rm0, off));
            rm1 = fmaxf(rm1, __shfl_xor_sync(0xffffffffu, rm1, off));
        }

        // ---- online softmax: P = exp2(s - m) via f16x2 MUFU ----
        float mn0 = fmaxf(m0, rm0), mn1 = fmaxf(m1, rm1);
        float al0 = ex2_f(m0 - mn0), al1 = ex2_f(m1 - mn1);
        unsigned plo[8], phi[8];
        #pragma unroll
        for (int ni = 0; ni < 8; ni++) {
            plo[ni] = ex2_h2(h2u(s[ni][0] - mn0, s[ni][1] - mn0));
            phi[ni] = ex2_h2(h2u(s[ni][2] - mn1, s[ni][3] - mn1));
        }

        // Row sums via ones-mma: ls = P @ 1 (fp32 accum, consistent with P)
        float ls[4] = {0.f, 0.f, 0.f, 0.f};
        #pragma unroll
        for (int t = 0; t < 4; t++)
            mma_f16(ls, plo[2*t], phi[2*t], plo[2*t+1], phi[2*t+1],
                    0x3C003C00u, 0x3C003C00u);
        l0 = l0 * al0 + ls[0];
        l1 = l1 * al1 + ls[2];
        m0 = mn0; m1 = mn1;

        #pragma unroll
        for (int dj = 0; dj < 8; dj++) {
            o[dj][0] *= al0; o[dj][1] *= al0;
            o[dj][2] *= al1; o[dj][3] *= al1;
        }

        // ---- O += P @ V  (P fragments = plo/phi directly; V ldmatrix.trans) ----
        #pragma unroll
        for (int t = 0; t < 4; t++) {    // k16 block over keys 16t..16t+15
            int row = 16 * t + (lane & 15);
            #pragma unroll
            for (int dj = 0; dj < 8; dj++) {
                unsigned addr = smem_u32(Vs + row * 64 + ((dj ^ (row & 7)) << 3));
                unsigned b0, b1;
                ldmx2t(b0, b1, addr);
                mma_f16(o[dj], plo[2*t], phi[2*t], plo[2*t+1], phi[2*t+1], b0, b1);
            }
        }
        __syncthreads();   // all warps done with buffer before it refills
    }

    // Epilogue: O / l -> g_att in fp16 A-frag layout [k16][m16][lane][4xhalf2].
    float inv0 = 1.0f / l0, inv1 = 1.0f / l1;
    int mg = b * (SEQ / 16) + qb * 8 + w;
    #pragma unroll
    for (int dj = 0; dj < 8; dj++) {
        int kg16 = h * 4 + (dj >> 1);
        __half* p = g_att + ((size_t)(kg16 * (MROWS / 16) + mg) * 32 + lane) * 8
                          + (dj & 1) * 4;
        *(unsigned*)(p)     = h2u(o[dj][0] * inv0, o[dj][1] * inv0);
        *(unsigned*)(p + 2) = h2u(o[dj][2] * inv1, o[dj][3] * inv1);
    }
}

extern "C" void kernel_launch(void* const* d_in, const int* in_sizes, int n_in,
                              void* d_out, int out_size)
{
    const float* x      = (const float*)d_in[0];
    const float* amask  = (const float*)d_in[1];
    const float* w_attn = (const float*)d_in[2];
    const float* b_attn = (const float*)d_in[3];
    const float* w_proj = (const float*)d_in[4];
    const float* b_proj = (const float*)d_in[5];
    float* out = (float*)d_out;

    // Device addresses of __device__ symbols (round-4 lesson).
    __half *gx, *gwa, *gwp, *gatt;
    cudaGetSymbolAddress((void**)&gx,   g_x);
    cudaGetSymbolAddress((void**)&gwa,  g_wa);
    cudaGetSymbolAddress((void**)&gwp,  g_wp);
    cudaGetSymbolAddress((void**)&gatt, g_att);

    // 0) pack inputs into fp16 fragment layouts
    packA_kernel<<<(48 * 256 * 32) / 256, 256>>>(x, gx, MROWS, NXC);
    packB_kernel<<<(48 * 288 * 32) / 256, 256>>>(w_attn, gwa, NXC, QKVN);
    packB_kernel<<<(48 * 96 * 32) / 256, 256>>>(w_proj, gwp, NXC, NXC);

    // 1) QKV projection -> g_qkv halves (Q pre-scaled by 0.125*log2e)
    gemm_tc<1><<<dim3(QKVN / 128, MROWS / 128), 256>>>(
        gx, gwa, b_attn, nullptr, MROWS, QKVN, NXC);

    // 2) Flash attention (32 KB static smem); writes g_att frag-packed fp16
    attn_kernel<<<dim3(SEQ / 128, NH, BSZ), 256>>>(amask);

    // 3) Output projection -> d_out (fp32)
    gemm_tc<0><<<dim3(NXC / 128, MROWS / 128), 256>>>(
        gatt, gwp, b_proj, out, MROWS, NXC, NXC);
}

// round 11
// speedup vs baseline: 8.1550x; 1.0993x over previous
#include <cuda_runtime.h>
#include <cuda_fp16.h>
#include <math.h>

#define SEQ   2048
#define NXC   768
#define NH    12
#define HD    64
#define BSZ   2
#define MROWS (BSZ*NXC == 0 ? 0 : BSZ*SEQ)   // 4096
#define QKVN  (3*NXC)        // 2304

#define LOG2E  1.4426950408889634f
#define MASKEDL (-10000.0f * LOG2E)

// Scratch (static __device__ — no allocations allowed). fp16 unless noted.
__device__ __align__(16) __half g_qkv[3ull * 4096 * NXC];
__device__ __align__(16) __half g_att[(size_t)4096 * NXC];
__device__ __align__(16) __half g_x [(size_t)4096 * NXC];
__device__ __align__(16) __half g_wa[(size_t)NXC * QKVN];
__device__ __align__(16) __half g_wp[(size_t)NXC * NXC];
// Split-KV partials for qb>=10: [piece][item=(b*NH+h)*6+(qb-10)]
__device__ __align__(16) float g_pO[2][BSZ*NH*6][128*64];
__device__ float g_pM[2][BSZ*NH*6][128];
__device__ float g_pL[2][BSZ*NH*6][128];

// Work-item tables: 22 items per (b,h), sorted heaviest-first.
// pc==-1: full item (2qb+2 tiles). pc 0/1: key-range halves (qb+1 tiles).
__device__ const signed char ITEM_QB[22] =
    {9,8,15,15,7,14,14,13,13,6,12,12,5,11,11,10,10,4,3,2,1,0};
__device__ const signed char ITEM_PC[22] =
    {-1,-1,0,1,-1,0,1,0,1,-1,0,1,-1,0,1,0,1,-1,-1,-1,-1,-1};

__device__ __forceinline__ unsigned h2u(float lo, float hi) {
    __half2 h = __floats2half2_rn(lo, hi);
    return *reinterpret_cast<unsigned*>(&h);
}

__device__ __forceinline__ void mma_f16(float* d,
    unsigned a0, unsigned a1, unsigned a2, unsigned a3,
    unsigned b0, unsigned b1)
{
    asm volatile(
        "mma.sync.aligned.m16n8k16.row.col.f32.f16.f16.f32 "
        "{%0,%1,%2,%3},{%4,%5,%6,%7},{%8,%9},{%0,%1,%2,%3};"
        : "+f"(d[0]), "+f"(d[1]), "+f"(d[2]), "+f"(d[3])
        : "r"(a0), "r"(a1), "r"(a2), "r"(a3), "r"(b0), "r"(b1));
}

__device__ __forceinline__ void ldmx2t(unsigned& r0, unsigned& r1, unsigned addr) {
    asm volatile("ldmatrix.sync.aligned.m8n8.x2.trans.shared.b16 {%0,%1}, [%2];"
                 : "=r"(r0), "=r"(r1) : "r"(addr));
}

__device__ __forceinline__ unsigned ex2_h2(unsigned x) {
    unsigned r;
    asm("ex2.approx.f16x2 %0, %1;" : "=r"(r) : "r"(x));
    return r;
}
__device__ __forceinline__ float ex2_f(float x) {
    float r;
    asm("ex2.approx.f32 %0, %1;" : "=f"(r) : "f"(x));
    return r;
}

__device__ __forceinline__ void cp16(unsigned dst, const void* src) {
    asm volatile("cp.async.cg.shared.global [%0], [%1], 16;"
                 :: "r"(dst), "l"(src));
}
#define CP_COMMIT()  asm volatile("cp.async.commit_group;")
#define CP_WAIT(n)   asm volatile("cp.async.wait_group " #n ";")
__device__ __forceinline__ unsigned smem_u32(const void* p) {
    return (unsigned)__cvta_generic_to_shared(p);
}

// ---------------------------------------------------------------------------
// Pack kernels (frozen)
// ---------------------------------------------------------------------------
__global__ void packA_kernel(const float* __restrict__ src, __half* __restrict__ dst,
                             int M, int K)
{
    int idx = blockIdx.x * blockDim.x + threadIdx.x;
    int lane = idx & 31;
    int mg   = (idx >> 5) & ((M / 16) - 1);
    int kb   = idx / (32 * (M / 16));
    if (kb >= K / 16) return;
    int lq = lane >> 2, lr = lane & 3;
    const float* s = src + (size_t)(mg * 16 + lq) * K + kb * 16 + 2 * lr;
    uint4 v;
    v.x = h2u(s[0],         s[1]);
    v.y = h2u(s[8 * K],     s[8 * K + 1]);
    v.z = h2u(s[8],         s[9]);
    v.w = h2u(s[8 * K + 8], s[8 * K + 9]);
    *(uint4*)(dst + (size_t)idx * 8) = v;
}

__global__ void packB_kernel(const float* __restrict__ src, __half* __restrict__ dst,
                             int K, int N)
{
    int idx = blockIdx.x * blockDim.x + threadIdx.x;
    int lane = idx & 31;
    int ng   = (idx >> 5) % (N / 8);
    int kb   = idx / (32 * (N / 8));
    if (kb >= K / 16) return;
    int lq = lane >> 2, lr = lane & 3;
    const float* s = src + (size_t)(kb * 16 + 2 * lr) * N + ng * 8 + lq;
    uint2 v;
    v.x = h2u(s[0],     s[N]);
    v.y = h2u(s[8 * N], s[9 * N]);
    *(uint2*)(dst + (size_t)idx * 4) = v;
}

// ---------------------------------------------------------------------------
// fp16 GEMM on fragment-packed operands (frozen from round 10)
// ---------------------------------------------------------------------------
template<int SPLITOUT>
__global__ void __launch_bounds__(256, 2)
gemm_tc(const __half* __restrict__ A, const __half* __restrict__ B,
        const float* __restrict__ bias, float* __restrict__ C,
        int M, int N, int K)
{
    __shared__ __half sg[24576];
    __half* As = sg;
    __half* Bs = sg + 12288;

    int tid  = threadIdx.x;
    int lane = tid & 31;
    int w    = tid >> 5;
    int wm   = w & 1;
    int wn   = w >> 1;
    int lq   = lane >> 2;
    int lr   = lane & 3;

    int brow16 = blockIdx.y * 8;
    int bcol8  = blockIdx.x * 16;
    const int M16 = M / 16, N8 = N / 8;

    float acc[4][4][4];
    #pragma unroll
    for (int mi = 0; mi < 4; mi++)
        #pragma unroll
        for (int ni = 0; ni < 4; ni++)
            #pragma unroll
            for (int j = 0; j < 4; j++) acc[mi][ni][j] = 0.f;

    const int NT = K / 32;

    auto issue = [&](int t, int s) {
        __half* as = As + s * 4096;
        __half* bs = Bs + s * 4096;
        const __half* gA = A + ((size_t)(2 * t) * M16 + brow16) * 256 + tid * 8;
        cp16(smem_u32(as + tid * 8),        gA);
        cp16(smem_u32(as + 2048 + tid * 8), gA + (size_t)M16 * 256);
        const __half* gB = B + ((size_t)(2 * t) * N8 + bcol8) * 128 + tid * 8;
        cp16(smem_u32(bs + tid * 8),        gB);
        cp16(smem_u32(bs + 2048 + tid * 8), gB + (size_t)N8 * 128);
        CP_COMMIT();
    };

    issue(0, 0);
    issue(1, 1);

    for (int t = 0; t < NT; t++) {
        CP_WAIT(1);
        __syncthreads();
        if (t + 2 < NT) issue(t + 2, (t + 2) % 3);

        const __half* as0 = As + (t % 3) * 4096 + wm * 1024 + lane * 8;
        const __half* bs0 = Bs + (t % 3) * 4096 + wn * 512 + lane * 4;
        #pragma unroll
        for (int kk = 0; kk < 2; kk++) {
            const __half* as = as0 + kk * 2048;
            const __half* bs = bs0 + kk * 2048;
            uint4 af[4];
            #pragma unroll
            for (int mi = 0; mi < 4; mi++)
                af[mi] = *(const uint4*)(as + mi * 256);
            #pragma unroll
            for (int ni = 0; ni < 4; ni++) {
                uint2 bf = *(const uint2*)(bs + ni * 128);
                #pragma unroll
                for (int mi = 0; mi < 4; mi++)
                    mma_f16(acc[mi][ni], af[mi].x, af[mi].y, af[mi].z, af[mi].w,
                            bf.x, bf.y);
            }
        }
    }

    #pragma unroll
    for (int mi = 0; mi < 4; mi++) {
        int r0 = brow16 * 16 + wm * 64 + mi * 16 + lq;
        #pragma unroll
        for (int ni = 0; ni < 4; ni++) {
            int col = bcol8 * 8 + wn * 32 + ni * 8 + lr * 2;
            float bv0 = bias[col], bv1 = bias[col + 1];
            float v00 = acc[mi][ni][0] + bv0, v01 = acc[mi][ni][1] + bv1;
            float v10 = acc[mi][ni][2] + bv0, v11 = acc[mi][ni][3] + bv1;
            if (SPLITOUT == 0) {
                *(float2*)(C + (size_t)r0 * N + col) = make_float2(v00, v01);
                *(float2*)(C + (size_t)(r0 + 8) * N + col) = make_float2(v10, v11);
            } else {
                int part = col / NXC;
                int c = col - part * NXC;
                float sc = (part == 0) ? (0.125f * LOG2E) : 1.0f;
                __half* dst = g_qkv + (size_t)part * 4096 * NXC + c;
                *(unsigned*)(dst + (size_t)r0 * NXC) = h2u(v00 * sc, v01 * sc);
                *(unsigned*)(dst + (size_t)(r0 + 8) * NXC) = h2u(v10 * sc, v11 * sc);
            }
        }
    }
}

// ---------------------------------------------------------------------------
// Flash attention with split-KV load balancing. Work item = (b, h, table idx):
// full item (qb<=9) computes all keys and writes g_att; split items (qb>=10)
// compute one key-half and write unnormalized partial (O, m, l) to scratch.
// Core per-tile math identical to round 10.
// ---------------------------------------------------------------------------
__global__ void __launch_bounds__(256, 2) attn_kernel(const float* __restrict__ amask)
{
    __shared__ __half kvs[2][2][4096];

    int h  = blockIdx.x;
    int b  = blockIdx.y;
    int item = blockIdx.z;          // slowest dim -> heavy items launch first
    int qb = ITEM_QB[item];
    int pc = ITEM_PC[item];
    int tid  = threadIdx.x;
    int lane = tid & 31;
    int w    = tid >> 5;
    int lq   = lane >> 2;
    int lr   = lane & 3;

    const size_t bh = (size_t)b * SEQ * NXC + (size_t)h * SEQ * HD;
    const __half* Qg = g_qkv + bh;
    const __half* Kg = g_qkv + (size_t)4096 * NXC + bh;
    const __half* Vg = g_qkv + 2ull * 4096 * NXC + bh;
    const float* am = amask + (size_t)b * SEQ;

    int kb0, kbN;
    if (pc < 0)      { kb0 = 0;      kbN = 2 * qb + 2; }
    else if (pc == 0){ kb0 = 0;      kbN = qb + 1; }
    else             { kb0 = qb + 1; kbN = 2 * qb + 2; }

    // Persistent Q fragments (fp16, pre-scaled by 0.125*log2e)
    int qrow = qb * 128 + w * 16 + lq;
    const __half* qr  = Qg + (size_t)qrow * HD;
    const __half* qr8 = Qg + (size_t)(qrow + 8) * HD;
    unsigned qa[4][4];
    #pragma unroll
    for (int ks = 0; ks < 4; ks++) {
        qa[ks][0] = *(const unsigned*)(qr  + ks * 16 + 2 * lr);
        qa[ks][1] = *(const unsigned*)(qr8 + ks * 16 + 2 * lr);
        qa[ks][2] = *(const unsigned*)(qr  + ks * 16 + 2 * lr + 8);
        qa[ks][3] = *(const unsigned*)(qr8 + ks * 16 + 2 * lr + 8);
    }

    float o[8][4];
    #pragma unroll
    for (int dj = 0; dj < 8; dj++)
        #pragma unroll
        for (int j = 0; j < 4; j++) o[dj][j] = 0.f;
    float m0 = -INFINITY, m1 = -INFINITY, l0 = 0.f, l1 = 0.f;

    auto issue = [&](int kb) {
        __half* kd = kvs[kb & 1][0];
        __half* vd = kvs[kb & 1][1];
        const __half* kg = Kg + (size_t)kb * 64 * HD;
        const __half* vg = Vg + (size_t)kb * 64 * HD;
        #pragma unroll
        for (int i = 0; i < 2; i++) {
            int f = tid + i * 256;
            int r = f >> 3, c = f & 7;
            int sw = r * 64 + ((c ^ (r & 7)) << 3);
            cp16(smem_u32(kd + sw), kg + r * 64 + c * 8);
            cp16(smem_u32(vd + sw), vg + r * 64 + c * 8);
        }
        CP_COMMIT();
    };

    issue(kb0);

    for (int kb = kb0; kb < kbN; kb++) {
        if (kb + 1 < kbN) issue(kb + 1);
        CP_WAIT(1);
        __syncthreads();

        const __half* Ks = kvs[kb & 1][0];
        const __half* Vs = kvs[kb & 1][1];

        float s[8][4];
        #pragma unroll
        for (int ni = 0; ni < 8; ni++)
            #pragma unroll
            for (int j = 0; j < 4; j++) s[ni][j] = 0.f;

        #pragma unroll
        for (int ks = 0; ks < 4; ks++) {
            #pragma unroll
            for (int ni = 0; ni < 8; ni++) {
                int key = ni * 8 + lq;
                const __half* base = Ks + key * 64 + 2 * lr;
                unsigned b0 = *(const unsigned*)(base + (((2*ks  ) ^ (key & 7)) << 3));
                unsigned b1 = *(const unsigned*)(base + (((2*ks+1) ^ (key & 7)) << 3));
                mma_f16(s[ni], qa[ks][0], qa[ks][1], qa[ks][2], qa[ks][3], b0, b1);
            }
        }

        bool need_mask = (kb >= 2 * qb);
        float rm0 = -INFINITY, rm1 = -INFINITY;
        #pragma unroll
        for (int ni = 0; ni < 8; ni++) {
            int gc0 = kb * 64 + ni * 8 + 2 * lr;
            float2 amv = *(const float2*)(am + gc0);
            float b00 = s[ni][0], b01 = s[ni][1];
            float b10 = s[ni][2], b11 = s[ni][3];
            if (need_mask) {
                if (gc0     > qrow)     b00 = MASKEDL;
                if (gc0 + 1 > qrow)     b01 = MASKEDL;
                if (gc0     > qrow + 8) b10 = MASKEDL;
                if (gc0 + 1 > qrow + 8) b11 = MASKEDL;
            }
            float v00 = fmaf(amv.x, LOG2E, b00);
            float v01 = fmaf(amv.y, LOG2E, b01);
            float v10 = fmaf(amv.x, LOG2E, b10);
            float v11 = fmaf(amv.y, LOG2E, b11);
            s[ni][0] = v00; s[ni][1] = v01; s[ni][2] = v10; s[ni][3] = v11;
            rm0 = fmaxf(rm0, fmaxf(v00, v01));
            rm1 = fmaxf(rm1, fmaxf(v10, v11));
        }
        #pragma unroll
        for (int off = 1; off <= 2; off <<= 1) {
            rm0 = fmaxf(rm0, __shfl_xor_sync(0xffffffffu, rm0, off));
            rm1 = fmaxf(rm1, __shfl_xor_sync(0xffffffffu, rm1, off));
        }

        float mn0 = fmaxf(m0, rm0), mn1 = fmaxf(m1, rm1);
        float al0 = ex2_f(m0 - mn0), al1 = ex2_f(m1 - mn1);
        unsigned plo[8], phi[8];
        #pragma unroll
        for (int ni = 0; ni < 8; ni++) {
            plo[ni] = ex2_h2(h2u(s[ni][0] - mn0, s[ni][1] - mn0));
            phi[ni] = ex2_h2(h2u(s[ni][2] - mn1, s[ni][3] - mn1));
        }

        float ls[4] = {0.f, 0.f, 0.f, 0.f};
        #pragma unroll
        for (int t = 0; t < 4; t++)
            mma_f16(ls, plo[2*t], phi[2*t], plo[2*t+1], phi[2*t+1],
                    0x3C003C00u, 0x3C003C00u);
        l0 = l0 * al0 + ls[0];
        l1 = l1 * al1 + ls[2];
        m0 = mn0; m1 = mn1;

        #pragma unroll
        for (int dj = 0; dj < 8; dj++) {
            o[dj][0] *= al0; o[dj][1] *= al0;
            o[dj][2] *= al1; o[dj][3] *= al1;
        }

        #pragma unroll
        for (int t = 0; t < 4; t++) {
            int row = 16 * t + (lane & 15);
            #pragma unroll
            for (int dj = 0; dj < 8; dj++) {
                unsigned addr = smem_u32(Vs + row * 64 + ((dj ^ (row & 7)) << 3));
                unsigned b0, b1;
                ldmx2t(b0, b1, addr);
                mma_f16(o[dj], plo[2*t], phi[2*t], plo[2*t+1], phi[2*t+1], b0, b1);
            }
        }
        __syncthreads();
    }

    if (pc < 0) {
        // Full item: normalize, write g_att frag-packed.
        float inv0 = 1.0f / l0, inv1 = 1.0f / l1;
        int mg = b * (SEQ / 16) + qb * 8 + w;
        #pragma unroll
        for (int dj = 0; dj < 8; dj++) {
            int kg16 = h * 4 + (dj >> 1);
            __half* p = g_att + ((size_t)(kg16 * 256 + mg) * 32 + lane) * 8
                              + (dj & 1) * 4;
            *(unsigned*)(p)     = h2u(o[dj][0] * inv0, o[dj][1] * inv0);
            *(unsigned*)(p + 2) = h2u(o[dj][2] * inv1, o[dj][3] * inv1);
        }
    } else {
        // Split piece: write unnormalized partial (O, m, l).
        int it = (b * NH + h) * 6 + (qb - 10);
        int prow = w * 16 + lq;
        #pragma unroll
        for (int dj = 0; dj < 8; dj++) {
            int col0 = dj * 8 + 2 * lr;
            *(float2*)&g_pO[pc][it][prow * 64 + col0] =
                make_float2(o[dj][0], o[dj][1]);
            *(float2*)&g_pO[pc][it][(prow + 8) * 64 + col0] =
                make_float2(o[dj][2], o[dj][3]);
        }
        if (lr == 0) {
            g_pM[pc][it][prow]     = m0;
            g_pM[pc][it][prow + 8] = m1;
            g_pL[pc][it][prow]     = l0;
            g_pL[pc][it][prow + 8] = l1;
        }
    }
}

// ---------------------------------------------------------------------------
// Combine split-KV partials -> g_att (frag-packed fp16). Grid (6, NH, BSZ).
// ---------------------------------------------------------------------------
__global__ void __launch_bounds__(256) combine_kernel()
{
    int qb = 10 + blockIdx.x;
    int h  = blockIdx.y;
    int b  = blockIdx.z;
    int it = (b * NH + h) * 6 + blockIdx.x;

    int tid  = threadIdx.x;
    int row  = tid >> 1;            // 0..127
    int c0   = (tid & 1) * 32;      // col half

    float m1 = g_pM[0][it][row], m2 = g_pM[1][it][row];
    float lA = g_pL[0][it][row], lB = g_pL[1][it][row];
    float ms = fmaxf(m1, m2);
    float a1 = ex2_f(m1 - ms), a2 = ex2_f(m2 - ms);
    float inv = 1.0f / (lA * a1 + lB * a2);
    float s1 = a1 * inv, s2 = a2 * inv;

    int grow = b * SEQ + qb * 128 + row;
    int mg = grow >> 4;
    int rq = grow & 15;
    int lqf = rq & 7, rowhi = rq >> 3;

    const float* O1 = &g_pO[0][it][row * 64 + c0];
    const float* O2 = &g_pO[1][it][row * 64 + c0];

    #pragma unroll
    for (int j = 0; j < 32; j += 2) {
        float2 v1 = *(const float2*)(O1 + j);
        float2 v2 = *(const float2*)(O2 + j);
        float val0 = v1.x * s1 + v2.x * s2;
        float val1 = v1.y * s1 + v2.y * s2;
        int col = c0 + j;
        int cg = h * 64 + col;
        int kb16 = cg >> 4;
        int cq = cg & 15;
        int lrf = (cq & 7) >> 1, chi = cq >> 3;
        __half* p = g_att + ((size_t)(kb16 * 256 + mg) * 32 + lqf * 4 + lrf) * 8
                          + chi * 4 + rowhi * 2;
        *(unsigned*)p = h2u(val0, val1);
    }
}

extern "C" void kernel_launch(void* const* d_in, const int* in_sizes, int n_in,
                              void* d_out, int out_size)
{
    const float* x      = (const float*)d_in[0];
    const float* amask  = (const float*)d_in[1];
    const float* w_attn = (const float*)d_in[2];
    const float* b_attn = (const float*)d_in[3];
    const float* w_proj = (const float*)d_in[4];
    const float* b_proj = (const float*)d_in[5];
    float* out = (float*)d_out;

    // Device addresses of __device__ symbols (round-4 lesson).
    __half *gx, *gwa, *gwp, *gatt;
    cudaGetSymbolAddress((void**)&gx,   g_x);
    cudaGetSymbolAddress((void**)&gwa,  g_wa);
    cudaGetSymbolAddress((void**)&gwp,  g_wp);
    cudaGetSymbolAddress((void**)&gatt, g_att);

    // 0) pack inputs into fp16 fragment layouts
    packA_kernel<<<(48 * 256 * 32) / 256, 256>>>(x, gx, 4096, NXC);
    packB_kernel<<<(48 * 288 * 32) / 256, 256>>>(w_attn, gwa, NXC, QKVN);
    packB_kernel<<<(48 * 96 * 32) / 256, 256>>>(w_proj, gwp, NXC, NXC);

    // 1) QKV projection -> g_qkv halves (Q pre-scaled by 0.125*log2e)
    gemm_tc<1><<<dim3(QKVN / 128, 4096 / 128), 256>>>(
        gx, gwa, b_attn, nullptr, 4096, QKVN, NXC);

    // 2) Flash attention, split-KV balanced (22 items per (b,h))
    attn_kernel<<<dim3(NH, BSZ, 22), 256>>>(amask);

    // 2b) Combine the split pieces
    combine_kernel<<<dim3(6, NH, BSZ), 256>>>();

    // 3) Output projection -> d_out (fp32)
    gemm_tc<0><<<dim3(NXC / 128, 4096 / 128), 256>>>(
        gatt, gwp, b_proj, out, 4096, NXC, NXC);
}

// round 14
// speedup vs baseline: 8.4824x; 1.0401x over previous
#include <cuda_runtime.h>
#include <cuda_fp16.h>
#include <stdint.h>
#include <math.h>

#define SEQ   2048
#define NXC   768
#define NH    12
#define HD    64
#define BSZ   2
#define MROWS 4096
#define QKVN  (3*NXC)        // 2304

#define LOG2E  1.4426950408889634f
#define MASKEDL (-10000.0f * LOG2E)

// Scratch (static __device__ — no allocations allowed). All fp16.
// g_qkv: [3][MROWS][NXC] row-major (Q pre-scaled by 0.125*log2e).
// g_att: proj-A fragment-packed [k16][m16][lane][4xhalf2]
// g_x:   A-frag packed;  g_wa/g_wp: B-frag packed [k16][n8][lane][2xhalf2]
__device__ __align__(16) __half g_qkv[3ull * MROWS * NXC];
__device__ __align__(16) __half g_att[(size_t)MROWS * NXC];
__device__ __align__(16) __half g_x [(size_t)MROWS * NXC];
__device__ __align__(16) __half g_wa[(size_t)NXC * QKVN];
__device__ __align__(16) __half g_wp[(size_t)NXC * NXC];
// Split-KV partials for qb>=10
__device__ __align__(16) float g_pO[2][BSZ*NH*6][128*64];
__device__ float g_pM[2][BSZ*NH*6][128];
__device__ float g_pL[2][BSZ*NH*6][128];

__device__ const signed char ITEM_QB[22] =
    {9,8,15,15,7,14,14,13,13,6,12,12,5,11,11,10,10,4,3,2,1,0};
__device__ const signed char ITEM_PC[22] =
    {-1,-1,0,1,-1,0,1,0,1,-1,0,1,-1,0,1,0,1,-1,-1,-1,-1,-1};

__device__ __forceinline__ unsigned h2u(float lo, float hi) {
    __half2 h = __floats2half2_rn(lo, hi);
    return *reinterpret_cast<unsigned*>(&h);
}

__device__ __forceinline__ void mma_f16(float* d,
    unsigned a0, unsigned a1, unsigned a2, unsigned a3,
    unsigned b0, unsigned b1)
{
    asm volatile(
        "mma.sync.aligned.m16n8k16.row.col.f32.f16.f16.f32 "
        "{%0,%1,%2,%3},{%4,%5,%6,%7},{%8,%9},{%0,%1,%2,%3};"
        : "+f"(d[0]), "+f"(d[1]), "+f"(d[2]), "+f"(d[3])
        : "r"(a0), "r"(a1), "r"(a2), "r"(a3), "r"(b0), "r"(b1));
}

__device__ __forceinline__ void ldmx4(unsigned& r0, unsigned& r1,
                                      unsigned& r2, unsigned& r3, unsigned addr) {
    asm volatile("ldmatrix.sync.aligned.m8n8.x4.shared.b16 {%0,%1,%2,%3}, [%4];"
                 : "=r"(r0), "=r"(r1), "=r"(r2), "=r"(r3) : "r"(addr));
}
__device__ __forceinline__ void ldmx4t(unsigned& r0, unsigned& r1,
                                       unsigned& r2, unsigned& r3, unsigned addr) {
    asm volatile("ldmatrix.sync.aligned.m8n8.x4.trans.shared.b16 {%0,%1,%2,%3}, [%4];"
                 : "=r"(r0), "=r"(r1), "=r"(r2), "=r"(r3) : "r"(addr));
}

__device__ __forceinline__ unsigned ex2_h2(unsigned x) {
    unsigned r; asm("ex2.approx.f16x2 %0, %1;" : "=r"(r) : "r"(x)); return r;
}
__device__ __forceinline__ float ex2_f(float x) {
    float r; asm("ex2.approx.f32 %0, %1;" : "=f"(r) : "f"(x)); return r;
}
__device__ __forceinline__ void cp16(unsigned dst, const void* src) {
    asm volatile("cp.async.cg.shared.global [%0], [%1], 16;"
                 :: "r"(dst), "l"(src));
}
#define CP_COMMIT()  asm volatile("cp.async.commit_group;")
#define CP_WAIT(n)   asm volatile("cp.async.wait_group " #n ";")
__device__ __forceinline__ unsigned smem_u32(const void* p) {
    return (unsigned)__cvta_generic_to_shared(p);
}

// ---------------------------------------------------------------------------
// Pack kernels: fp16-round AND permute into m16n8k16 fragment order.
// ---------------------------------------------------------------------------
__global__ void packA_kernel(const float* __restrict__ src, __half* __restrict__ dst,
                             int M, int K)
{
    int idx = blockIdx.x * blockDim.x + threadIdx.x;
    int lane = idx & 31;
    int mg   = (idx >> 5) & ((M / 16) - 1);
    int kb   = idx / (32 * (M / 16));
    if (kb >= K / 16) return;
    int lq = lane >> 2, lr = lane & 3;
    const float* s = src + (size_t)(mg * 16 + lq) * K + kb * 16 + 2 * lr;
    uint4 v;
    v.x = h2u(s[0],         s[1]);
    v.y = h2u(s[8 * K],     s[8 * K + 1]);
    v.z = h2u(s[8],         s[9]);
    v.w = h2u(s[8 * K + 8], s[8 * K + 9]);
    *(uint4*)(dst + (size_t)idx * 8) = v;
}

__global__ void packB_kernel(const float* __restrict__ src, __half* __restrict__ dst,
                             int K, int N)
{
    int idx = blockIdx.x * blockDim.x + threadIdx.x;
    int lane = idx & 31;
    int ng   = (idx >> 5) % (N / 8);
    int kb   = idx / (32 * (N / 8));
    if (kb >= K / 16) return;
    int lq = lane >> 2, lr = lane & 3;
    const float* s = src + (size_t)(kb * 16 + 2 * lr) * N + ng * 8 + lq;
    uint2 v;
    v.x = h2u(s[0],     s[N]);
    v.y = h2u(s[8 * N], s[9 * N]);
    *(uint2*)(dst + (size_t)idx * 4) = v;
}

// ---------------------------------------------------------------------------
// fp16 GEMM on fragment-packed operands. BK=64 (4 k16 slabs/stage),
// 3-stage cp.async (96 KB dynamic smem), 8 warps (2m x 4n), warp tile 64x32.
// SPLITOUT=1: fp16 scatter into g_qkv (Q pre-scaled). SPLITOUT=0: fp32 + bias.
// ---------------------------------------------------------------------------
#define GSTG_H 8192          // halves per stage per operand (4 slabs x 2048)
#define GSMEM_DYN (6 * GSTG_H * 2)   // 98304 B

template<int SPLITOUT>
__global__ void __launch_bounds__(256, 2)
gemm_tc(const __half* __restrict__ A, const __half* __restrict__ B,
        const float* __restrict__ bias, float* __restrict__ C,
        int M, int N, int K)
{
    extern __shared__ __half sg[];
    __half* As = sg;                 // [3][GSTG_H]
    __half* Bs = sg + 3 * GSTG_H;

    int tid  = threadIdx.x;
    int lane = tid & 31;
    int w    = tid >> 5;
    int wm   = w & 1;
    int wn   = w >> 1;
    int lq   = lane >> 2;
    int lr   = lane & 3;

    int brow16 = blockIdx.y * 8;
    int bcol8  = blockIdx.x * 16;
    const int M16 = M / 16, N8 = N / 8;

    float acc[4][4][4];
    #pragma unroll
    for (int mi = 0; mi < 4; mi++)
        #pragma unroll
        for (int ni = 0; ni < 4; ni++)
            #pragma unroll
            for (int j = 0; j < 4; j++) acc[mi][ni][j] = 0.f;

    const int NT = K / 64;    // 12

    auto issue = [&](int t, int s) {
        __half* as = As + s * GSTG_H;
        __half* bs = Bs + s * GSTG_H;
        #pragma unroll
        for (int j = 0; j < 4; j++) {
            const __half* gA = A + ((size_t)(4 * t + j) * M16 + brow16) * 256 + tid * 8;
            cp16(smem_u32(as + j * 2048 + tid * 8), gA);
            const __half* gB = B + ((size_t)(4 * t + j) * N8 + bcol8) * 128 + tid * 8;
            cp16(smem_u32(bs + j * 2048 + tid * 8), gB);
        }
        CP_COMMIT();
    };

    issue(0, 0);
    issue(1, 1);

    for (int t = 0; t < NT; t++) {
        CP_WAIT(1);
        __syncthreads();
        if (t + 2 < NT) issue(t + 2, (t + 2) % 3);

        const __half* as0 = As + (t % 3) * GSTG_H + wm * 1024 + lane * 8;
        const __half* bs0 = Bs + (t % 3) * GSTG_H + wn * 512 + lane * 4;
        #pragma unroll
        for (int kk = 0; kk < 4; kk++) {
            const __half* as = as0 + kk * 2048;
            const __half* bs = bs0 + kk * 2048;
            uint4 af[4];
            #pragma unroll
            for (int mi = 0; mi < 4; mi++)
                af[mi] = *(const uint4*)(as + mi * 256);
            #pragma unroll
            for (int ni = 0; ni < 4; ni++) {
                uint2 bf = *(const uint2*)(bs + ni * 128);
                #pragma unroll
                for (int mi = 0; mi < 4; mi++)
                    mma_f16(acc[mi][ni], af[mi].x, af[mi].y, af[mi].z, af[mi].w,
                            bf.x, bf.y);
            }
        }
    }

    // Epilogue
    #pragma unroll
    for (int mi = 0; mi < 4; mi++) {
        int r0 = brow16 * 16 + wm * 64 + mi * 16 + lq;
        #pragma unroll
        for (int ni = 0; ni < 4; ni++) {
            int col = bcol8 * 8 + wn * 32 + ni * 8 + lr * 2;
            float bv0 = bias[col], bv1 = bias[col + 1];
            float v00 = acc[mi][ni][0] + bv0, v01 = acc[mi][ni][1] + bv1;
            float v10 = acc[mi][ni][2] + bv0, v11 = acc[mi][ni][3] + bv1;
            if (SPLITOUT == 0) {
                *(float2*)(C + (size_t)r0 * N + col) = make_float2(v00, v01);
                *(float2*)(C + (size_t)(r0 + 8) * N + col) = make_float2(v10, v11);
            } else {
                int part = col / NXC;
                int c = col - part * NXC;
                float sc = (part == 0) ? (0.125f * LOG2E) : 1.0f;
                __half* dst = g_qkv + (size_t)part * MROWS * NXC + c;
                *(unsigned*)(dst + (size_t)r0 * NXC) = h2u(v00 * sc, v01 * sc);
                *(unsigned*)(dst + (size_t)(r0 + 8) * NXC) = h2u(v10 * sc, v11 * sc);
            }
        }
    }
}

// ---------------------------------------------------------------------------
// Flash attention with split-KV balancing (round-11 structure).
// S-phase K fragments via ldmatrix.x4; PV V fragments via ldmatrix.x4.trans.
// ---------------------------------------------------------------------------
__global__ void __launch_bounds__(256, 2) attn_kernel(const float* __restrict__ amask)
{
    __shared__ __half kvs[2][2][4096];

    int h  = blockIdx.x;
    int b  = blockIdx.y;
    int item = blockIdx.z;
    int qb = ITEM_QB[item];
    int pc = ITEM_PC[item];
    int tid  = threadIdx.x;
    int lane = tid & 31;
    int w    = tid >> 5;
    int lq   = lane >> 2;
    int lr   = lane & 3;

    const size_t bh = (size_t)b * SEQ * NXC + (size_t)h * SEQ * HD;
    const __half* Qg = g_qkv + bh;
    const __half* Kg = g_qkv + (size_t)MROWS * NXC + bh;
    const __half* Vg = g_qkv + 2ull * MROWS * NXC + bh;
    const float* am = amask + (size_t)b * SEQ;

    int kb0, kbN;
    if (pc < 0)      { kb0 = 0;      kbN = 2 * qb + 2; }
    else if (pc == 0){ kb0 = 0;      kbN = qb + 1; }
    else             { kb0 = qb + 1; kbN = 2 * qb + 2; }

    int qrow = qb * 128 + w * 16 + lq;
    const __half* qr  = Qg + (size_t)qrow * HD;
    const __half* qr8 = Qg + (size_t)(qrow + 8) * HD;
    unsigned qa[4][4];
    #pragma unroll
    for (int ks = 0; ks < 4; ks++) {
        qa[ks][0] = *(const unsigned*)(qr  + ks * 16 + 2 * lr);
        qa[ks][1] = *(const unsigned*)(qr8 + ks * 16 + 2 * lr);
        qa[ks][2] = *(const unsigned*)(qr  + ks * 16 + 2 * lr + 8);
        qa[ks][3] = *(const unsigned*)(qr8 + ks * 16 + 2 * lr + 8);
    }

    float o[8][4];
    #pragma unroll
    for (int dj = 0; dj < 8; dj++)
        #pragma unroll
        for (int j = 0; j < 4; j++) o[dj][j] = 0.f;
    float m0 = -INFINITY, m1 = -INFINITY, l0 = 0.f, l1 = 0.f;

    auto issue = [&](int kb) {
        __half* kd = kvs[kb & 1][0];
        __half* vd = kvs[kb & 1][1];
        const __half* kg = Kg + (size_t)kb * 64 * HD;
        const __half* vg = Vg + (size_t)kb * 64 * HD;
        #pragma unroll
        for (int i = 0; i < 2; i++) {
            int f = tid + i * 256;
            int r = f >> 3, c = f & 7;
            int sw = r * 64 + ((c ^ (r & 7)) << 3);
            cp16(smem_u32(kd + sw), kg + r * 64 + c * 8);
            cp16(smem_u32(vd + sw), vg + r * 64 + c * 8);
        }
        CP_COMMIT();
    };

    issue(kb0);

    for (int kb = kb0; kb < kbN; kb++) {
        if (kb + 1 < kbN) issue(kb + 1);
        CP_WAIT(1);
        __syncthreads();

        const __half* Ks = kvs[kb & 1][0];
        const __half* Vs = kvs[kb & 1][1];

        // ---- S = Q @ K^T : K b-frags via ldmatrix.x4 ----
        float s[8][4];
        #pragma unroll
        for (int ni = 0; ni < 8; ni++)
            #pragma unroll
            for (int j = 0; j < 4; j++) s[ni][j] = 0.f;

        {
            int keyrow = lane & 7;        // row within 8-key group
            int cgrp   = lane >> 3;       // k-chunk 0..3
            #pragma unroll
            for (int ni = 0; ni < 8; ni++) {
                int key = ni * 8 + keyrow;
                const __half* kr = Ks + key * 64;
                unsigned kf[8];
                ldmx4(kf[0], kf[1], kf[2], kf[3],
                      smem_u32(kr + ((cgrp ^ (key & 7)) << 3)));
                ldmx4(kf[4], kf[5], kf[6], kf[7],
                      smem_u32(kr + (((cgrp + 4) ^ (key & 7)) << 3)));
                #pragma unroll
                for (int ks = 0; ks < 4; ks++)
                    mma_f16(s[ni], qa[ks][0], qa[ks][1], qa[ks][2], qa[ks][3],
                            kf[2 * ks], kf[2 * ks + 1]);
            }
        }

        // ---- causal mask + attention_mask*log2e + row max ----
        bool need_mask = (kb >= 2 * qb);
        float rm0 = -INFINITY, rm1 = -INFINITY;
        #pragma unroll
        for (int ni = 0; ni < 8; ni++) {
            int gc0 = kb * 64 + ni * 8 + 2 * lr;
            float2 amv = *(const float2*)(am + gc0);
            float b00 = s[ni][0], b01 = s[ni][1];
            float b10 = s[ni][2], b11 = s[ni][3];
            if (need_mask) {
                if (gc0     > qrow)     b00 = MASKEDL;
                if (gc0 + 1 > qrow)     b01 = MASKEDL;
                if (gc0     > qrow + 8) b10 = MASKEDL;
                if (gc0 + 1 > qrow + 8) b11 = MASKEDL;
            }
            float v00 = fmaf(amv.x, LOG2E, b00);
            float v01 = fmaf(amv.y, LOG2E, b01);
            float v10 = fmaf(amv.x, LOG2E, b10);
            float v11 = fmaf(amv.y, LOG2E, b11);
            s[ni][0] = v00; s[ni][1] = v01; s[ni][2] = v10; s[ni][3] = v11;
            rm0 = fmaxf(rm0, fmaxf(v00, v01));
            rm1 = fmaxf(rm1, fmaxf(v10, v11));
        }
        #pragma unroll
        for (int off = 1; off <= 2; off <<= 1) {
            rm0 = fmaxf(rm0, __shfl_xor_sync(0xffffffffu, rm0, off));
            rm1 = fmaxf(rm1, __shfl_xor_sync(0xffffffffu, rm1, off));
        }

        // ---- online softmax: P = exp2(s - m) via f16x2 MUFU ----
        float mn0 = fmaxf(m0, rm0), mn1 = fmaxf(m1, rm1);
        float al0 = ex2_f(m0 - mn0), al1 = ex2_f(m1 - mn1);
        unsigned plo[8], phi[8];
        #pragma unroll
        for (int ni = 0; ni < 8; ni++) {
            plo[ni] = ex2_h2(h2u(s[ni][0] - mn0, s[ni][1] - mn0));
            phi[ni] = ex2_h2(h2u(s[ni][2] - mn1, s[ni][3] - mn1));
        }

        // Row sums via ones-mma
        float ls[4] = {0.f, 0.f, 0.f, 0.f};
        #pragma unroll
        for (int t = 0; t < 4; t++)
            mma_f16(ls, plo[2*t], phi[2*t], plo[2*t+1], phi[2*t+1],
                    0x3C003C00u, 0x3C003C00u);
        l0 = l0 * al0 + ls[0];
        l1 = l1 * al1 + ls[2];
        m0 = mn0; m1 = mn1;

        #pragma unroll
        for (int dj = 0; dj < 8; dj++) {
            o[dj][0] *= al0; o[dj][1] *= al0;
            o[dj][2] *= al1; o[dj][3] *= al1;
        }

        // ---- O += P @ V : V b-frags via ldmatrix.x4.trans (dj pairs) ----
        #pragma unroll
        for (int t = 0; t < 4; t++) {
            int row = 16 * t + (lane & 15);
            int cadd = lane >> 4;          // 0: dj, 1: dj+1
            #pragma unroll
            for (int dj = 0; dj < 8; dj += 2) {
                int c = dj + cadd;
                unsigned b0, b1, b2, b3;
                ldmx4t(b0, b1, b2, b3,
                       smem_u32(Vs + row * 64 + ((c ^ (row & 7)) << 3)));
                mma_f16(o[dj],     plo[2*t], phi[2*t], plo[2*t+1], phi[2*t+1], b0, b1);
                mma_f16(o[dj + 1], plo[2*t], phi[2*t], plo[2*t+1], phi[2*t+1], b2, b3);
            }
        }
        __syncthreads();
    }

    if (pc < 0) {
        // Full item: normalize, write g_att frag-packed.
        float inv0 = 1.0f / l0, inv1 = 1.0f / l1;
        int mg = b * (SEQ / 16) + qb * 8 + w;
        #pragma unroll
        for (int dj = 0; dj < 8; dj++) {
            int kg16 = h * 4 + (dj >> 1);
            __half* p = g_att + ((size_t)(kg16 * (MROWS / 16) + mg) * 32 + lane) * 8
                              + (dj & 1) * 4;
            *(unsigned*)(p)     = h2u(o[dj][0] * inv0, o[dj][1] * inv0);
            *(unsigned*)(p + 2) = h2u(o[dj][2] * inv1, o[dj][3] * inv1);
        }
    } else {
        int it = (b * NH + h) * 6 + (qb - 10);
        int prow = w * 16 + lq;
        #pragma unroll
        for (int dj = 0; dj < 8; dj++) {
            int col0 = dj * 8 + 2 * lr;
            *(float2*)&g_pO[pc][it][prow * 64 + col0] =
                make_float2(o[dj][0], o[dj][1]);
            *(float2*)&g_pO[pc][it][(prow + 8) * 64 + col0] =
                make_float2(o[dj][2], o[dj][3]);
        }
        if (lr == 0) {
            g_pM[pc][it][prow]     = m0;
            g_pM[pc][it][prow + 8] = m1;
            g_pL[pc][it][prow]     = l0;
            g_pL[pc][it][prow + 8] = l1;
        }
    }
}

// ---------------------------------------------------------------------------
// Combine split-KV partials -> g_att (frag-packed fp16). Grid (6, NH, BSZ).
// ---------------------------------------------------------------------------
__global__ void __launch_bounds__(256) combine_kernel()
{
    int qb = 10 + blockIdx.x;
    int h  = blockIdx.y;
    int b  = blockIdx.z;
    int it = (b * NH + h) * 6 + blockIdx.x;

    int tid  = threadIdx.x;
    int row  = tid >> 1;
    int c0   = (tid & 1) * 32;

    float m1 = g_pM[0][it][row], m2 = g_pM[1][it][row];
    float lA = g_pL[0][it][row], lB = g_pL[1][it][row];
    float ms = fmaxf(m1, m2);
    float a1 = ex2_f(m1 - ms), a2 = ex2_f(m2 - ms);
    float inv = 1.0f / (lA * a1 + lB * a2);
    float s1 = a1 * inv, s2 = a2 * inv;

    int grow = b * SEQ + qb * 128 + row;
    int mg = grow >> 4;
    int rq = grow & 15;
    int lqf = rq & 7, rowhi = rq >> 3;

    const float* O1 = &g_pO[0][it][row * 64 + c0];
    const float* O2 = &g_pO[1][it][row * 64 + c0];

    #pragma unroll
    for (int j = 0; j < 32; j += 2) {
        float2 v1 = *(const float2*)(O1 + j);
        float2 v2 = *(const float2*)(O2 + j);
        float val0 = v1.x * s1 + v2.x * s2;
        float val1 = v1.y * s1 + v2.y * s2;
        int cg = h * 64 + c0 + j;
        int kb16 = cg >> 4;
        int cq = cg & 15;
        int lrf = (cq & 7) >> 1, chi = cq >> 3;
        __half* p = g_att + ((size_t)(kb16 * (MROWS / 16) + mg) * 32 + lqf * 4 + lrf) * 8
                          + chi * 4 + rowhi * 2;
        *(unsigned*)p = h2u(val0, val1);
    }
}

extern "C" void kernel_launch(void* const* d_in, const int* in_sizes, int n_in,
                              void* d_out, int out_size)
{
    const float* x      = (const float*)d_in[0];
    const float* amask  = (const float*)d_in[1];
    const float* w_attn = (const float*)d_in[2];
    const float* b_attn = (const float*)d_in[3];
    const float* w_proj = (const float*)d_in[4];
    const float* b_proj = (const float*)d_in[5];
    float* out = (float*)d_out;

    // Device addresses of __device__ symbols (round-4 lesson).
    __half *gx, *gwa, *gwp, *gatt;
    cudaGetSymbolAddress((void**)&gx,   g_x);
    cudaGetSymbolAddress((void**)&gwa,  g_wa);
    cudaGetSymbolAddress((void**)&gwp,  g_wp);
    cudaGetSymbolAddress((void**)&gatt, g_att);

    // 0) pack inputs into fp16 fragment layouts
    packA_kernel<<<(48 * 256 * 32) / 256, 256>>>(x, gx, MROWS, NXC);
    packB_kernel<<<(48 * 288 * 32) / 256, 256>>>(w_attn, gwa, NXC, QKVN);
    packB_kernel<<<(48 * 96 * 32) / 256, 256>>>(w_proj, gwp, NXC, NXC);

    cudaFuncSetAttribute(gemm_tc<1>,
                         cudaFuncAttributeMaxDynamicSharedMemorySize, GSMEM_DYN);
    cudaFuncSetAttribute(gemm_tc<0>,
                         cudaFuncAttributeMaxDynamicSharedMemorySize, GSMEM_DYN);

    // 1) QKV projection -> g_qkv halves (Q pre-scaled by 0.125*log2e)
    gemm_tc<1><<<dim3(QKVN / 128, MROWS / 128), 256, GSMEM_DYN>>>(
        gx, gwa, b_attn, nullptr, MROWS, QKVN, NXC);

    // 2) Flash attention, split-KV balanced
    attn_kernel<<<dim3(NH, BSZ, 22), 256>>>(amask);

    // 2b) Combine split pieces
    combine_kernel<<<dim3(6, NH, BSZ), 256>>>();

    // 3) Output projection -> d_out (fp32)
    gemm_tc<0><<<dim3(NXC / 128, MROWS / 128), 256, GSMEM_DYN>>>(
        gatt, gwp, b_proj, out, MROWS, NXC, NXC);
}

// round 15
// speedup vs baseline: 8.7525x; 1.0318x over previous
#include <cuda_runtime.h>
#include <cuda_fp16.h>
#include <stdint.h>
#include <math.h>

#define SEQ   2048
#define NXC   768
#define NH    12
#define HD    64
#define BSZ   2
#define MROWS 4096
#define QKVN  (3*NXC)        // 2304

#define LOG2E  1.4426950408889634f
#define MASKEDL (-10000.0f * LOG2E)

// Scratch (static __device__ — no allocations allowed). All fp16.
__device__ __align__(16) __half g_qkv[3ull * MROWS * NXC];
__device__ __align__(16) __half g_att[(size_t)MROWS * NXC];
__device__ __align__(16) __half g_x [(size_t)MROWS * NXC];
__device__ __align__(16) __half g_wa[(size_t)NXC * QKVN];
__device__ __align__(16) __half g_wp[(size_t)NXC * NXC];
// Split-KV partials for qb>=10
__device__ __align__(16) float g_pO[2][BSZ*NH*6][128*64];
__device__ float g_pM[2][BSZ*NH*6][128];
__device__ float g_pL[2][BSZ*NH*6][128];

__device__ const signed char ITEM_QB[22] =
    {9,8,15,15,7,14,14,13,13,6,12,12,5,11,11,10,10,4,3,2,1,0};
__device__ const signed char ITEM_PC[22] =
    {-1,-1,0,1,-1,0,1,0,1,-1,0,1,-1,0,1,0,1,-1,-1,-1,-1,-1};

__device__ __forceinline__ unsigned h2u(float lo, float hi) {
    __half2 h = __floats2half2_rn(lo, hi);
    return *reinterpret_cast<unsigned*>(&h);
}

__device__ __forceinline__ void mma_f16(float* d,
    unsigned a0, unsigned a1, unsigned a2, unsigned a3,
    unsigned b0, unsigned b1)
{
    asm volatile(
        "mma.sync.aligned.m16n8k16.row.col.f32.f16.f16.f32 "
        "{%0,%1,%2,%3},{%4,%5,%6,%7},{%8,%9},{%0,%1,%2,%3};"
        : "+f"(d[0]), "+f"(d[1]), "+f"(d[2]), "+f"(d[3])
        : "r"(a0), "r"(a1), "r"(a2), "r"(a3), "r"(b0), "r"(b1));
}

__device__ __forceinline__ void ldmx4(unsigned& r0, unsigned& r1,
                                      unsigned& r2, unsigned& r3, unsigned addr) {
    asm volatile("ldmatrix.sync.aligned.m8n8.x4.shared.b16 {%0,%1,%2,%3}, [%4];"
                 : "=r"(r0), "=r"(r1), "=r"(r2), "=r"(r3) : "r"(addr));
}
__device__ __forceinline__ void ldmx4t(unsigned& r0, unsigned& r1,
                                       unsigned& r2, unsigned& r3, unsigned addr) {
    asm volatile("ldmatrix.sync.aligned.m8n8.x4.trans.shared.b16 {%0,%1,%2,%3}, [%4];"
                 : "=r"(r0), "=r"(r1), "=r"(r2), "=r"(r3) : "r"(addr));
}

__device__ __forceinline__ unsigned ex2_h2(unsigned x) {
    unsigned r; asm("ex2.approx.f16x2 %0, %1;" : "=r"(r) : "r"(x)); return r;
}
__device__ __forceinline__ float ex2_f(float x) {
    float r; asm("ex2.approx.f32 %0, %1;" : "=f"(r) : "f"(x)); return r;
}
__device__ __forceinline__ void cp16(unsigned dst, const void* src) {
    asm volatile("cp.async.cg.shared.global [%0], [%1], 16;"
                 :: "r"(dst), "l"(src));
}
#define CP_COMMIT()  asm volatile("cp.async.commit_group;")
#define CP_WAIT(n)   asm volatile("cp.async.wait_group " #n ";")
__device__ __forceinline__ unsigned smem_u32(const void* p) {
    return (unsigned)__cvta_generic_to_shared(p);
}

// ---------------------------------------------------------------------------
// Fused pack kernel: one launch covers packA(x) + packB(w_attn) + packB(w_proj).
// ---------------------------------------------------------------------------
__device__ __forceinline__ void packA_body(const float* __restrict__ src,
                                           __half* __restrict__ dst,
                                           int idx, int M, int K)
{
    int lane = idx & 31;
    int mg   = (idx >> 5) & ((M / 16) - 1);
    int kb   = idx / (32 * (M / 16));
    if (kb >= K / 16) return;
    int lq = lane >> 2, lr = lane & 3;
    const float* s = src + (size_t)(mg * 16 + lq) * K + kb * 16 + 2 * lr;
    uint4 v;
    v.x = h2u(s[0],         s[1]);
    v.y = h2u(s[8 * K],     s[8 * K + 1]);
    v.z = h2u(s[8],         s[9]);
    v.w = h2u(s[8 * K + 8], s[8 * K + 9]);
    *(uint4*)(dst + (size_t)idx * 8) = v;
}

__device__ __forceinline__ void packB_body(const float* __restrict__ src,
                                           __half* __restrict__ dst,
                                           int idx, int K, int N)
{
    int lane = idx & 31;
    int ng   = (idx >> 5) % (N / 8);
    int kb   = idx / (32 * (N / 8));
    if (kb >= K / 16) return;
    int lq = lane >> 2, lr = lane & 3;
    const float* s = src + (size_t)(kb * 16 + 2 * lr) * N + ng * 8 + lq;
    uint2 v;
    v.x = h2u(s[0],     s[N]);
    v.y = h2u(s[8 * N], s[9 * N]);
    *(uint2*)(dst + (size_t)idx * 4) = v;
}

#define PACKA_BLKS 1536      // 48*256*32/256
#define PACKWA_BLKS 1728     // 48*288*32/256
#define PACKWP_BLKS 576      // 48*96*32/256

__global__ void pack_all_kernel(const float* __restrict__ x,
                                const float* __restrict__ wa,
                                const float* __restrict__ wp,
                                __half* __restrict__ gx,
                                __half* __restrict__ gwa,
                                __half* __restrict__ gwp)
{
    int bid = blockIdx.x;
    if (bid < PACKA_BLKS) {
        packA_body(x, gx, bid * 256 + threadIdx.x, MROWS, NXC);
    } else if (bid < PACKA_BLKS + PACKWA_BLKS) {
        packB_body(wa, gwa, (bid - PACKA_BLKS) * 256 + threadIdx.x, NXC, QKVN);
    } else {
        packB_body(wp, gwp, (bid - PACKA_BLKS - PACKWA_BLKS) * 256 + threadIdx.x,
                   NXC, NXC);
    }
}

// ---------------------------------------------------------------------------
// fp16 GEMM on fragment-packed operands (frozen from round 14). BK=64,
// 3-stage cp.async (96 KB dynamic smem), 8 warps (2m x 4n), warp tile 64x32.
// ---------------------------------------------------------------------------
#define GSTG_H 8192
#define GSMEM_DYN (6 * GSTG_H * 2)   // 98304 B

template<int SPLITOUT>
__global__ void __launch_bounds__(256, 2)
gemm_tc(const __half* __restrict__ A, const __half* __restrict__ B,
        const float* __restrict__ bias, float* __restrict__ C,
        int M, int N, int K)
{
    extern __shared__ __half sg[];
    __half* As = sg;
    __half* Bs = sg + 3 * GSTG_H;

    int tid  = threadIdx.x;
    int lane = tid & 31;
    int w    = tid >> 5;
    int wm   = w & 1;
    int wn   = w >> 1;
    int lq   = lane >> 2;
    int lr   = lane & 3;

    int brow16 = blockIdx.y * 8;
    int bcol8  = blockIdx.x * 16;
    const int M16 = M / 16, N8 = N / 8;

    float acc[4][4][4];
    #pragma unroll
    for (int mi = 0; mi < 4; mi++)
        #pragma unroll
        for (int ni = 0; ni < 4; ni++)
            #pragma unroll
            for (int j = 0; j < 4; j++) acc[mi][ni][j] = 0.f;

    const int NT = K / 64;

    auto issue = [&](int t, int s) {
        __half* as = As + s * GSTG_H;
        __half* bs = Bs + s * GSTG_H;
        #pragma unroll
        for (int j = 0; j < 4; j++) {
            const __half* gA = A + ((size_t)(4 * t + j) * M16 + brow16) * 256 + tid * 8;
            cp16(smem_u32(as + j * 2048 + tid * 8), gA);
            const __half* gB = B + ((size_t)(4 * t + j) * N8 + bcol8) * 128 + tid * 8;
            cp16(smem_u32(bs + j * 2048 + tid * 8), gB);
        }
        CP_COMMIT();
    };

    issue(0, 0);
    issue(1, 1);

    for (int t = 0; t < NT; t++) {
        CP_WAIT(1);
        __syncthreads();
        if (t + 2 < NT) issue(t + 2, (t + 2) % 3);

        const __half* as0 = As + (t % 3) * GSTG_H + wm * 1024 + lane * 8;
        const __half* bs0 = Bs + (t % 3) * GSTG_H + wn * 512 + lane * 4;
        #pragma unroll
        for (int kk = 0; kk < 4; kk++) {
            const __half* as = as0 + kk * 2048;
            const __half* bs = bs0 + kk * 2048;
            uint4 af[4];
            #pragma unroll
            for (int mi = 0; mi < 4; mi++)
                af[mi] = *(const uint4*)(as + mi * 256);
            #pragma unroll
            for (int ni = 0; ni < 4; ni++) {
                uint2 bf = *(const uint2*)(bs + ni * 128);
                #pragma unroll
                for (int mi = 0; mi < 4; mi++)
                    mma_f16(acc[mi][ni], af[mi].x, af[mi].y, af[mi].z, af[mi].w,
                            bf.x, bf.y);
            }
        }
    }

    #pragma unroll
    for (int mi = 0; mi < 4; mi++) {
        int r0 = brow16 * 16 + wm * 64 + mi * 16 + lq;
        #pragma unroll
        for (int ni = 0; ni < 4; ni++) {
            int col = bcol8 * 8 + wn * 32 + ni * 8 + lr * 2;
            float bv0 = bias[col], bv1 = bias[col + 1];
            float v00 = acc[mi][ni][0] + bv0, v01 = acc[mi][ni][1] + bv1;
            float v10 = acc[mi][ni][2] + bv0, v11 = acc[mi][ni][3] + bv1;
            if (SPLITOUT == 0) {
                *(float2*)(C + (size_t)r0 * N + col) = make_float2(v00, v01);
                *(float2*)(C + (size_t)(r0 + 8) * N + col) = make_float2(v10, v11);
            } else {
                int part = col / NXC;
                int c = col - part * NXC;
                float sc = (part == 0) ? (0.125f * LOG2E) : 1.0f;
                __half* dst = g_qkv + (size_t)part * MROWS * NXC + c;
                *(unsigned*)(dst + (size_t)r0 * NXC) = h2u(v00 * sc, v01 * sc);
                *(unsigned*)(dst + (size_t)(r0 + 8) * NXC) = h2u(v10 * sc, v11 * sc);
            }
        }
    }
}

// ---------------------------------------------------------------------------
// Flash attention with split-KV balancing. Single-barrier pipeline:
// CP_WAIT(0) -> syncthreads -> issue(kb+1) -> compute(kb). Masked/unmasked
// tile paths split (warp-uniform). Core math identical to round 14.
// ---------------------------------------------------------------------------
__global__ void __launch_bounds__(256, 2) attn_kernel(const float* __restrict__ amask)
{
    __shared__ __half kvs[2][2][4096];

    int h  = blockIdx.x;
    int b  = blockIdx.y;
    int item = blockIdx.z;
    int qb = ITEM_QB[item];
    int pc = ITEM_PC[item];
    int tid  = threadIdx.x;
    int lane = tid & 31;
    int w    = tid >> 5;
    int lq   = lane >> 2;
    int lr   = lane & 3;

    const size_t bh = (size_t)b * SEQ * NXC + (size_t)h * SEQ * HD;
    const __half* Qg = g_qkv + bh;
    const __half* Kg = g_qkv + (size_t)MROWS * NXC + bh;
    const __half* Vg = g_qkv + 2ull * MROWS * NXC + bh;
    const float* am = amask + (size_t)b * SEQ;

    int kb0, kbN;
    if (pc < 0)      { kb0 = 0;      kbN = 2 * qb + 2; }
    else if (pc == 0){ kb0 = 0;      kbN = qb + 1; }
    else             { kb0 = qb + 1; kbN = 2 * qb + 2; }

    int qrow = qb * 128 + w * 16 + lq;
    const __half* qr  = Qg + (size_t)qrow * HD;
    const __half* qr8 = Qg + (size_t)(qrow + 8) * HD;
    unsigned qa[4][4];
    #pragma unroll
    for (int ks = 0; ks < 4; ks++) {
        qa[ks][0] = *(const unsigned*)(qr  + ks * 16 + 2 * lr);
        qa[ks][1] = *(const unsigned*)(qr8 + ks * 16 + 2 * lr);
        qa[ks][2] = *(const unsigned*)(qr  + ks * 16 + 2 * lr + 8);
        qa[ks][3] = *(const unsigned*)(qr8 + ks * 16 + 2 * lr + 8);
    }

    float o[8][4];
    #pragma unroll
    for (int dj = 0; dj < 8; dj++)
        #pragma unroll
        for (int j = 0; j < 4; j++) o[dj][j] = 0.f;
    float m0 = -INFINITY, m1 = -INFINITY, l0 = 0.f, l1 = 0.f;

    auto issue = [&](int kb) {
        __half* kd = kvs[kb & 1][0];
        __half* vd = kvs[kb & 1][1];
        const __half* kg = Kg + (size_t)kb * 64 * HD;
        const __half* vg = Vg + (size_t)kb * 64 * HD;
        #pragma unroll
        for (int i = 0; i < 2; i++) {
            int f = tid + i * 256;
            int r = f >> 3, c = f & 7;
            int sw = r * 64 + ((c ^ (r & 7)) << 3);
            cp16(smem_u32(kd + sw), kg + r * 64 + c * 8);
            cp16(smem_u32(vd + sw), vg + r * 64 + c * 8);
        }
        CP_COMMIT();
    };

    issue(kb0);

    for (int kb = kb0; kb < kbN; kb++) {
        CP_WAIT(0);          // stage kb data arrived (only its group outstanding)
        __syncthreads();     // all warps done with stage kb-1 -> buffer reuse safe
        if (kb + 1 < kbN) issue(kb + 1);   // overlaps with compute(kb)

        const __half* Ks = kvs[kb & 1][0];
        const __half* Vs = kvs[kb & 1][1];

        // ---- S = Q @ K^T : K b-frags via ldmatrix.x4 ----
        float s[8][4];
        #pragma unroll
        for (int ni = 0; ni < 8; ni++)
            #pragma unroll
            for (int j = 0; j < 4; j++) s[ni][j] = 0.f;

        {
            int keyrow = lane & 7;
            int cgrp   = lane >> 3;
            #pragma unroll
            for (int ni = 0; ni < 8; ni++) {
                int key = ni * 8 + keyrow;
                const __half* kr = Ks + key * 64;
                unsigned kf[8];
                ldmx4(kf[0], kf[1], kf[2], kf[3],
                      smem_u32(kr + ((cgrp ^ (key & 7)) << 3)));
                ldmx4(kf[4], kf[5], kf[6], kf[7],
                      smem_u32(kr + (((cgrp + 4) ^ (key & 7)) << 3)));
                #pragma unroll
                for (int ks = 0; ks < 4; ks++)
                    mma_f16(s[ni], qa[ks][0], qa[ks][1], qa[ks][2], qa[ks][3],
                            kf[2 * ks], kf[2 * ks + 1]);
            }
        }

        // ---- mask + attention_mask*log2e + row max (split paths) ----
        float rm0 = -INFINITY, rm1 = -INFINITY;
        if (kb >= 2 * qb) {
            // diagonal tiles: causal mask needed
            #pragma unroll
            for (int ni = 0; ni < 8; ni++) {
                int gc0 = kb * 64 + ni * 8 + 2 * lr;
                float2 amv = *(const float2*)(am + gc0);
                float b00 = s[ni][0], b01 = s[ni][1];
                float b10 = s[ni][2], b11 = s[ni][3];
                if (gc0     > qrow)     b00 = MASKEDL;
                if (gc0 + 1 > qrow)     b01 = MASKEDL;
                if (gc0     > qrow + 8) b10 = MASKEDL;
                if (gc0 + 1 > qrow + 8) b11 = MASKEDL;
                float v00 = fmaf(amv.x, LOG2E, b00);
                float v01 = fmaf(amv.y, LOG2E, b01);
                float v10 = fmaf(amv.x, LOG2E, b10);
                float v11 = fmaf(amv.y, LOG2E, b11);
                s[ni][0] = v00; s[ni][1] = v01; s[ni][2] = v10; s[ni][3] = v11;
                rm0 = fmaxf(rm0, fmaxf(v00, v01));
                rm1 = fmaxf(rm1, fmaxf(v10, v11));
            }
        } else {
            // interior tiles: no causal mask
            #pragma unroll
            for (int ni = 0; ni < 8; ni++) {
                int gc0 = kb * 64 + ni * 8 + 2 * lr;
                float2 amv = *(const float2*)(am + gc0);
                float v00 = fmaf(amv.x, LOG2E, s[ni][0]);
                float v01 = fmaf(amv.y, LOG2E, s[ni][1]);
                float v10 = fmaf(amv.x, LOG2E, s[ni][2]);
                float v11 = fmaf(amv.y, LOG2E, s[ni][3]);
                s[ni][0] = v00; s[ni][1] = v01; s[ni][2] = v10; s[ni][3] = v11;
                rm0 = fmaxf(rm0, fmaxf(v00, v01));
                rm1 = fmaxf(rm1, fmaxf(v10, v11));
            }
        }
        #pragma unroll
        for (int off = 1; off <= 2; off <<= 1) {
            rm0 = fmaxf(rm0, __shfl_xor_sync(0xffffffffu, rm0, off));
            rm1 = fmaxf(rm1, __shfl_xor_sync(0xffffffffu, rm1, off));
        }

        // ---- online softmax: P = exp2(s - m) via f16x2 MUFU ----
        float mn0 = fmaxf(m0, rm0), mn1 = fmaxf(m1, rm1);
        float al0 = ex2_f(m0 - mn0), al1 = ex2_f(m1 - mn1);
        unsigned plo[8], phi[8];
        #pragma unroll
        for (int ni = 0; ni < 8; ni++) {
            plo[ni] = ex2_h2(h2u(s[ni][0] - mn0, s[ni][1] - mn0));
            phi[ni] = ex2_h2(h2u(s[ni][2] - mn1, s[ni][3] - mn1));
        }

        // Row sums via ones-mma
        float ls[4] = {0.f, 0.f, 0.f, 0.f};
        #pragma unroll
        for (int t = 0; t < 4; t++)
            mma_f16(ls, plo[2*t], phi[2*t], plo[2*t+1], phi[2*t+1],
                    0x3C003C00u, 0x3C003C00u);
        l0 = l0 * al0 + ls[0];
        l1 = l1 * al1 + ls[2];
        m0 = mn0; m1 = mn1;

        #pragma unroll
        for (int dj = 0; dj < 8; dj++) {
            o[dj][0] *= al0; o[dj][1] *= al0;
            o[dj][2] *= al1; o[dj][3] *= al1;
        }

        // ---- O += P @ V : V b-frags via ldmatrix.x4.trans (dj pairs) ----
        #pragma unroll
        for (int t = 0; t < 4; t++) {
            int row = 16 * t + (lane & 15);
            int cadd = lane >> 4;
            #pragma unroll
            for (int dj = 0; dj < 8; dj += 2) {
                int c = dj + cadd;
                unsigned b0, b1, b2, b3;
                ldmx4t(b0, b1, b2, b3,
                       smem_u32(Vs + row * 64 + ((c ^ (row & 7)) << 3)));
                mma_f16(o[dj],     plo[2*t], phi[2*t], plo[2*t+1], phi[2*t+1], b0, b1);
                mma_f16(o[dj + 1], plo[2*t], phi[2*t], plo[2*t+1], phi[2*t+1], b2, b3);
            }
        }
    }

    if (pc < 0) {
        // Full item: normalize, write g_att frag-packed.
        float inv0 = 1.0f / l0, inv1 = 1.0f / l1;
        int mg = b * (SEQ / 16) + qb * 8 + w;
        #pragma unroll
        for (int dj = 0; dj < 8; dj++) {
            int kg16 = h * 4 + (dj >> 1);
            __half* p = g_att + ((size_t)(kg16 * (MROWS / 16) + mg) * 32 + lane) * 8
                              + (dj & 1) * 4;
            *(unsigned*)(p)     = h2u(o[dj][0] * inv0, o[dj][1] * inv0);
            *(unsigned*)(p + 2) = h2u(o[dj][2] * inv1, o[dj][3] * inv1);
        }
    } else {
        int it = (b * NH + h) * 6 + (qb - 10);
        int prow = w * 16 + lq;
        #pragma unroll
        for (int dj = 0; dj < 8; dj++) {
            int col0 = dj * 8 + 2 * lr;
            *(float2*)&g_pO[pc][it][prow * 64 + col0] =
                make_float2(o[dj][0], o[dj][1]);
            *(float2*)&g_pO[pc][it][(prow + 8) * 64 + col0] =
                make_float2(o[dj][2], o[dj][3]);
        }
        if (lr == 0) {
            g_pM[pc][it][prow]     = m0;
            g_pM[pc][it][prow + 8] = m1;
            g_pL[pc][it][prow]     = l0;
            g_pL[pc][it][prow + 8] = l1;
        }
    }
}

// ---------------------------------------------------------------------------
// Combine split-KV partials -> g_att (frag-packed fp16). Grid (6, NH, BSZ).
// ---------------------------------------------------------------------------
__global__ void __launch_bounds__(256) combine_kernel()
{
    int qb = 10 + blockIdx.x;
    int h  = blockIdx.y;
    int b  = blockIdx.z;
    int it = (b * NH + h) * 6 + blockIdx.x;

    int tid  = threadIdx.x;
    int row  = tid >> 1;
    int c0   = (tid & 1) * 32;

    float m1 = g_pM[0][it][row], m2 = g_pM[1][it][row];
    float lA = g_pL[0][it][row], lB = g_pL[1][it][row];
    float ms = fmaxf(m1, m2);
    float a1 = ex2_f(m1 - ms), a2 = ex2_f(m2 - ms);
    float inv = 1.0f / (lA * a1 + lB * a2);
    float s1 = a1 * inv, s2 = a2 * inv;

    int grow = b * SEQ + qb * 128 + row;
    int mg = grow >> 4;
    int rq = grow & 15;
    int lqf = rq & 7, rowhi = rq >> 3;

    const float* O1 = &g_pO[0][it][row * 64 + c0];
    const float* O2 = &g_pO[1][it][row * 64 + c0];

    #pragma unroll
    for (int j = 0; j < 32; j += 2) {
        float2 v1 = *(const float2*)(O1 + j);
        float2 v2 = *(const float2*)(O2 + j);
        float val0 = v1.x * s1 + v2.x * s2;
        float val1 = v1.y * s1 + v2.y * s2;
        int cg = h * 64 + c0 + j;
        int kb16 = cg >> 4;
        int cq = cg & 15;
        int lrf = (cq & 7) >> 1, chi = cq >> 3;
        __half* p = g_att + ((size_t)(kb16 * (MROWS / 16) + mg) * 32 + lqf * 4 + lrf) * 8
                          + chi * 4 + rowhi * 2;
        *(unsigned*)p = h2u(val0, val1);
    }
}

extern "C" void kernel_launch(void* const* d_in, const int* in_sizes, int n_in,
                              void* d_out, int out_size)
{
    const float* x      = (const float*)d_in[0];
    const float* amask  = (const float*)d_in[1];
    const float* w_attn = (const float*)d_in[2];
    const float* b_attn = (const float*)d_in[3];
    const float* w_proj = (const float*)d_in[4];
    const float* b_proj = (const float*)d_in[5];
    float* out = (float*)d_out;

    // Device addresses of __device__ symbols (round-4 lesson).
    __half *gx, *gwa, *gwp, *gatt;
    cudaGetSymbolAddress((void**)&gx,   g_x);
    cudaGetSymbolAddress((void**)&gwa,  g_wa);
    cudaGetSymbolAddress((void**)&gwp,  g_wp);
    cudaGetSymbolAddress((void**)&gatt, g_att);

    // 0) fused pack: all three inputs in one launch
    pack_all_kernel<<<PACKA_BLKS + PACKWA_BLKS + PACKWP_BLKS, 256>>>(
        x, w_attn, w_proj, gx, gwa, gwp);

    cudaFuncSetAttribute(gemm_tc<1>,
                         cudaFuncAttributeMaxDynamicSharedMemorySize, GSMEM_DYN);
    cudaFuncSetAttribute(gemm_tc<0>,
                         cudaFuncAttributeMaxDynamicSharedMemorySize, GSMEM_DYN);

    // 1) QKV projection -> g_qkv halves (Q pre-scaled by 0.125*log2e)
    gemm_tc<1><<<dim3(QKVN / 128, MROWS / 128), 256, GSMEM_DYN>>>(
        gx, gwa, b_attn, nullptr, MROWS, QKVN, NXC);

    // 2) Flash attention, split-KV balanced
    attn_kernel<<<dim3(NH, BSZ, 22), 256>>>(amask);

    // 2b) Combine split pieces
    combine_kernel<<<dim3(6, NH, BSZ), 256>>>();

    // 3) Output projection -> d_out (fp32)
    gemm_tc<0><<<dim3(NXC / 128, MROWS / 128), 256, GSMEM_DYN>>>(
        gatt, gwp, b_proj, out, MROWS, NXC, NXC);
}